// round 8
// baseline (speedup 1.0000x reference)
#include <cuda_runtime.h>

#define FULLMASK 0xffffffffu

__device__ __forceinline__ float warp_sum(float v) {
#pragma unroll
    for (int o = 16; o; o >>= 1) v += __shfl_xor_sync(FULLMASK, v, o);
    return v;
}
__device__ __forceinline__ float warp_max(float v) {
#pragma unroll
    for (int o = 16; o; o >>= 1) v = fmaxf(v, __shfl_xor_sync(FULLMASK, v, o));
    return v;
}

// ---------------- static scratch (16B-aligned: float4 access everywhere) ------
__device__ __align__(16) float g_P1q[1024 * 128];
__device__ __align__(16) float g_P1v[1024 * 128];
__device__ __align__(16) float g_AO1[1024 * 128];
__device__ __align__(16) float g_O1[1024 * 128];
__device__ __align__(16) float g_p[1024 * 128];
__device__ __align__(16) float g_Q4[32 * 128];
__device__ __align__(16) float g_K4[1024 * 128];
__device__ __align__(16) float g_V4[1024 * 128];
__device__ __align__(16) float g_K4t[1024 * 128];   // (B,H,DK,S)
__device__ __align__(16) float g_V4bh[1024 * 128];  // (B,H,S,DK)
__device__ __align__(16) float g_AO4[16384 * 128];
__device__ __align__(16) float g_O4[16384 * 128];

// ---- GEMM C[M][128] = A[M][128] @ W^T + b. Tile 32 rows x 64 cols, 256 thr.
__global__ __launch_bounds__(256) void gemm_kernel(
    const float* A0, const float* W0, const float* B0, float* C0, int M0,
    const float* A1, const float* W1, const float* B1, float* C1, int M1) {
    const float *A, *W, *Bv; float* C; int M;
    if (blockIdx.z == 0) { A = A0; W = W0; Bv = B0; C = C0; M = M0; }
    else                 { A = A1; W = W1; Bv = B1; C = C1; M = M1; }
    __shared__ __align__(16) float As[32 * 32];
    __shared__ __align__(16) float Ws[32 * 64];
    const int t = threadIdx.x;
    const int row0 = blockIdx.x * 32, c0 = blockIdx.y * 64;
    const int cx = t & 15, ry = t >> 4;
    float acc[2][4] = {};
    for (int kb = 0; kb < 128; kb += 32) {
        int lr = t >> 3, lk = (t & 7) * 4;
        if (row0 + lr < M)
            *(float4*)&As[lr * 32 + lk] = *(const float4*)&A[(size_t)(row0 + lr) * 128 + kb + lk];
        else
            *(float4*)&As[lr * 32 + lk] = make_float4(0.f, 0.f, 0.f, 0.f);
        int wc = t >> 2, wk = (t & 3) * 8;
        float4 w0 = *(const float4*)&W[(size_t)(c0 + wc) * 128 + kb + wk];
        float4 w1 = *(const float4*)&W[(size_t)(c0 + wc) * 128 + kb + wk + 4];
        Ws[(wk + 0) * 64 + wc] = w0.x; Ws[(wk + 1) * 64 + wc] = w0.y;
        Ws[(wk + 2) * 64 + wc] = w0.z; Ws[(wk + 3) * 64 + wc] = w0.w;
        Ws[(wk + 4) * 64 + wc] = w1.x; Ws[(wk + 5) * 64 + wc] = w1.y;
        Ws[(wk + 6) * 64 + wc] = w1.z; Ws[(wk + 7) * 64 + wc] = w1.w;
        __syncthreads();
#pragma unroll
        for (int k = 0; k < 32; k++) {
            float4 wv = *(const float4*)&Ws[k * 64 + cx * 4];
#pragma unroll
            for (int rr = 0; rr < 2; rr++) {
                float a = As[(ry * 2 + rr) * 32 + k];
                acc[rr][0] += a * wv.x; acc[rr][1] += a * wv.y;
                acc[rr][2] += a * wv.z; acc[rr][3] += a * wv.w;
            }
        }
        __syncthreads();
    }
    float4 bv = *(const float4*)&Bv[c0 + cx * 4];
#pragma unroll
    for (int rr = 0; rr < 2; rr++) {
        int row = row0 + ry * 2 + rr;
        if (row < M)
            *(float4*)&C[(size_t)row * 128 + c0 + cx * 4] =
                make_float4(acc[rr][0] + bv.x, acc[rr][1] + bv.y,
                            acc[rr][2] + bv.z, acc[rr][3] + bv.w);
    }
}

// ---- repack K4 -> (B,H,DK,S), V4 -> (B,H,S,DK)
__global__ __launch_bounds__(256) void repack_kernel() {
    int idx = blockIdx.x * 256 + threadIdx.x;  // 131072
    int hd = idx & 127, j = (idx >> 7) & 255, b = idx >> 15;
    int h = hd >> 4, dk = hd & 15;
    g_K4t[((size_t)((b * 8 + h) * 16 + dk)) * 256 + j] = g_K4[idx];
    g_V4bh[((size_t)((b * 8 + h) * 256 + j)) * 16 + dk] = g_V4[idx];
}

// ---- block1 attention (peek_cur=True, maxout=False). grid 256 = B*H*8chunks.
__global__ __launch_bounds__(256) void attn1_kernel(
    const float* __restrict__ gamma, float* __restrict__ qscore) {
    extern __shared__ __align__(16) float dyn[];
    float* Ks = dyn;                 // 256*20
    float* Vs = dyn + 5120;          // 256*20
    float* rowbuf = dyn + 10240;     // 8*256
    const int bx = blockIdx.x;
    const int chunk = bx & 7, h = (bx >> 3) & 7, b = bx >> 6;
    const int t = threadIdx.x, lane = t & 31, w = t >> 5;
    {
        const float* ksrc = g_P1q + ((size_t)(b * 256 + t)) * 128 + h * 16;
        const float* vsrc = g_P1v + ((size_t)(b * 256 + t)) * 128 + h * 16;
#pragma unroll
        for (int c = 0; c < 4; c++) {
            *(float4*)&Ks[t * 20 + c * 4] = *(const float4*)&ksrc[c * 4];
            *(float4*)&Vs[t * 20 + c * 4] = *(const float4*)&vsrc[c * 4];
        }
    }
    __syncthreads();
    const float ag = fabsf(gamma[h]);
    float* myrow = rowbuf + w * 256;
    for (int it = 0; it < 4; it++) {
        const int i = chunk * 32 + it * 8 + w;
        float q[16];
#pragma unroll
        for (int c = 0; c < 4; c++) {
            float4 qv = *(const float4*)&Ks[i * 20 + c * 4];
            q[c * 4] = qv.x; q[c * 4 + 1] = qv.y; q[c * 4 + 2] = qv.z; q[c * 4 + 3] = qv.w;
        }
        float sc[8], m1 = -3.0e38f;
#pragma unroll
        for (int u = 0; u < 8; u++) {
            int j = lane + 32 * u;
            float s = 0.f;
#pragma unroll
            for (int c = 0; c < 4; c++) {
                float4 kv = *(const float4*)&Ks[j * 20 + c * 4];
                s += q[c*4]*kv.x + q[c*4+1]*kv.y + q[c*4+2]*kv.z + q[c*4+3]*kv.w;
            }
            sc[u] = s * 0.25f;
            if (j <= i) m1 = fmaxf(m1, sc[u]);
        }
        m1 = warp_max(m1);
        float lsum = 0.f;
#pragma unroll
        for (int u = 0; u < 8; u++) {
            int j = lane + 32 * u;
            lsum += (j <= i) ? __expf(sc[u] - m1) : 0.f;
            myrow[j] = sc[u];
        }
        float inv1 = 1.f / warp_sum(lsum);
        __syncwarp();
        // blocked phase: lane owns j in [8*lane, 8*lane+8)
        float scb[8], eb[8], cpref[8], run = 0.f;
#pragma unroll
        for (int o = 0; o < 8; o++) {
            int j = lane * 8 + o;
            scb[o] = myrow[j];
            eb[o] = (j <= i) ? __expf(scb[o] - m1) : 0.f;
            run += eb[o]; cpref[o] = run;
        }
        float x = run;
#pragma unroll
        for (int d = 1; d < 32; d <<= 1) {
            float n = __shfl_up_sync(FULLMASK, x, d);
            if (lane >= d) x += n;
        }
        float excl = x - run;
        float s2[8], m2 = -3.0e38f;
#pragma unroll
        for (int o = 0; o < 8; o++) {
            int j = lane * 8 + o;
            bool valid = (j <= i);
            float c = (cpref[o] + excl) * inv1;
            float pos = valid ? (float)(i - j) : 0.f;
            float dist = sqrtf(fmaxf(1.f - c, 0.f) * pos);
            float eff = fmaxf(__expf(-ag * dist), 1e-5f);
            s2[o] = valid ? scb[o] * eff : -3.0e38f;
            m2 = fmaxf(m2, s2[o]);
        }
        m2 = warp_max(m2);
        float ww[8], ls = 0.f;
#pragma unroll
        for (int o = 0; o < 8; o++) { ww[o] = __expf(s2[o] - m2); ls += ww[o]; }
        float inv2 = 1.f / warp_sum(ls);
        float p[8];
#pragma unroll
        for (int o = 0; o < 8; o++) p[o] = ww[o] * inv2;
        float* qrow = qscore + ((size_t)((b * 8 + h) * 256 + i)) * 256;
        *(float4*)&qrow[lane * 8] = make_float4(p[0], p[1], p[2], p[3]);
        *(float4*)&qrow[lane * 8 + 4] = make_float4(p[4], p[5], p[6], p[7]);
        __syncwarp();
#pragma unroll
        for (int o = 0; o < 8; o++) myrow[lane * 8 + o] = p[o];
        __syncwarp();
        float acc[16];
#pragma unroll
        for (int d = 0; d < 16; d++) acc[d] = 0.f;
#pragma unroll
        for (int u = 0; u < 8; u++) {
            int j = lane + 32 * u;
            float pv = myrow[j];
#pragma unroll
            for (int c = 0; c < 4; c++) {
                float4 vv = *(const float4*)&Vs[j * 20 + c * 4];
                acc[c*4] += pv*vv.x; acc[c*4+1] += pv*vv.y;
                acc[c*4+2] += pv*vv.z; acc[c*4+3] += pv*vv.w;
            }
        }
#pragma unroll
        for (int o = 16; o; o >>= 1)
#pragma unroll
            for (int d = 0; d < 16; d++) acc[d] += __shfl_xor_sync(FULLMASK, acc[d], o);
        if (lane == 0) {
            float* dst = g_AO1 + ((size_t)(b * 256 + i)) * 128 + h * 16;
#pragma unroll
            for (int c = 0; c < 4; c++)
                *(float4*)&dst[c * 4] = make_float4(acc[c*4], acc[c*4+1], acc[c*4+2], acc[c*4+3]);
        }
        __syncwarp();
    }
}

// ---- block4 attention (peek_cur=False, maxout=True). Row-invariant scores.
__global__ __launch_bounds__(256) void attn4_kernel(
    const float* __restrict__ gamma, float* __restrict__ kscore) {
    __shared__ __align__(16) float Vs[256 * 20];   // declared first + aligned
    __shared__ float sc[256];
    __shared__ float qs[16];
    __shared__ float red[8];
    __shared__ float P[257];
    const int bx = blockIdx.x;
    const int h = bx & 7, nk = (bx >> 3) & 15, b = bx >> 7;
    const int t = threadIdx.x, lane = t & 31, w = t >> 5;
    if (t < 16) qs[t] = g_Q4[nk * 128 + h * 16 + t];
    __syncthreads();
    {
        const float* kb = g_K4t + ((size_t)((b * 8 + h) * 16)) * 256;
        float s = 0.f;
#pragma unroll
        for (int dk = 0; dk < 16; dk++) s += qs[dk] * kb[dk * 256 + t];
        sc[t] = s * 0.25f;
        const float* vsrc = g_V4bh + ((size_t)((b * 8 + h) * 256 + t)) * 16;
#pragma unroll
        for (int c = 0; c < 4; c++)
            *(float4*)&Vs[t * 20 + c * 4] = *(const float4*)&vsrc[c * 4];
    }
    __syncthreads();
    float myv = sc[t];
    float wm = warp_max(myv);
    if (lane == 0) red[w] = wm;
    __syncthreads();
    float M = red[0];
#pragma unroll
    for (int k = 1; k < 8; k++) M = fmaxf(M, red[k]);
    float e = __expf(myv - M);
    float v = e;
#pragma unroll
    for (int d = 1; d < 32; d <<= 1) {
        float n = __shfl_up_sync(FULLMASK, v, d);
        if (lane >= d) v += n;
    }
    __syncthreads();
    if (lane == 31) red[w] = v;
    __syncthreads();
    float off = 0.f;
    for (int k = 0; k < w; k++) off += red[k];
    P[t + 1] = v + off;
    if (t == 0) P[0] = 0.f;
    __syncthreads();
    const float ag = fabsf(gamma[h]);
    float* ksbase = kscore + ((size_t)(b * 8 + h)) * 1048576 + (size_t)nk * 256;
    for (int i = w; i < 256; i += 8) {
        float p[8];
        if (i == 0) {
#pragma unroll
            for (int u = 0; u < 8; u++) p[u] = 0.f;
        } else {
            float Ei = P[i], invE = 1.f / Ei;
            float s2[8], m2 = -3.0e38f;
#pragma unroll
            for (int u = 0; u < 8; u++) {
                int j = lane + 32 * u;
                bool valid = (j < i);
                float r = fmaxf((Ei - P[j + 1]) * invE, 0.f);
                float pos = valid ? (float)(i - j) : 0.f;
                float dist = sqrtf(r * pos);
                float eff = fmaxf(__expf(-ag * dist), 1e-5f);
                s2[u] = valid ? sc[j] * eff : -3.0e38f;
                m2 = fmaxf(m2, s2[u]);
            }
            m2 = warp_max(m2);
            float ls = 0.f, ww[8];
#pragma unroll
            for (int u = 0; u < 8; u++) { ww[u] = __expf(s2[u] - m2); ls += ww[u]; }
            float sum2 = warp_sum(ls);
            float f = fminf(sum2, 5.f) / sum2;   // maxout folded in
#pragma unroll
            for (int u = 0; u < 8; u++) p[u] = ww[u] * f;
        }
        float* krow = ksbase + (size_t)i * 4096;
#pragma unroll
        for (int u = 0; u < 8; u++) krow[lane + 32 * u] = p[u];
        float acc[16];
#pragma unroll
        for (int d = 0; d < 16; d++) acc[d] = 0.f;
#pragma unroll
        for (int u = 0; u < 8; u++) {
            int j = lane + 32 * u;
            float pv = p[u];
#pragma unroll
            for (int c = 0; c < 4; c++) {
                float4 vv = *(const float4*)&Vs[j * 20 + c * 4];
                acc[c*4] += pv*vv.x; acc[c*4+1] += pv*vv.y;
                acc[c*4+2] += pv*vv.z; acc[c*4+3] += pv*vv.w;
            }
        }
#pragma unroll
        for (int o = 16; o; o >>= 1)
#pragma unroll
            for (int d = 0; d < 16; d++) acc[d] += __shfl_xor_sync(FULLMASK, acc[d], o);
        if (lane == 0) {
            float* dst = g_AO4 + ((size_t)((b * 16 + nk) * 256 + i)) * 128 + h * 16;
#pragma unroll
            for (int c = 0; c < 4; c++)
                *(float4*)&dst[c * 4] = make_float4(acc[c*4], acc[c*4+1], acc[c*4+2], acc[c*4+3]);
        }
    }
}

// ---- p = LN(q_emb + O1)
__global__ __launch_bounds__(256) void ln_res_kernel(
    const float* __restrict__ x, const float* __restrict__ g,
    const float* __restrict__ bb) {
    int row = blockIdx.x * 8 + (threadIdx.x >> 5);
    int lane = threadIdx.x & 31;
    float4 xv = *(const float4*)&x[(size_t)row * 128 + lane * 4];
    float4 yv = *(const float4*)&g_O1[(size_t)row * 128 + lane * 4];
    float v0 = xv.x + yv.x, v1 = xv.y + yv.y, v2 = xv.z + yv.z, v3 = xv.w + yv.w;
    float mean = warp_sum(v0 + v1 + v2 + v3) * (1.f / 128.f);
    float d0 = v0 - mean, d1 = v1 - mean, d2 = v2 - mean, d3 = v3 - mean;
    float rstd = rsqrtf(warp_sum(d0*d0 + d1*d1 + d2*d2 + d3*d3) * (1.f/128.f) + 1e-5f);
    float4 gv = *(const float4*)&g[lane * 4];
    float4 bv = *(const float4*)&bb[lane * 4];
    *(float4*)&g_p[(size_t)row * 128 + lane * 4] =
        make_float4(d0*rstd*gv.x + bv.x, d1*rstd*gv.y + bv.y,
                    d2*rstd*gv.z + bv.z, d3*rstd*gv.w + bv.w);
}

// ---- z[b,i,nk*128+c] = LN(know[nk] + O4[(b*16+nk)*256+i])[c]
__global__ __launch_bounds__(256) void ln4_kernel(
    const float* __restrict__ know, const float* __restrict__ g,
    const float* __restrict__ bb, float* __restrict__ z) {
    int row = blockIdx.x * 8 + (threadIdx.x >> 5);  // 0..16383
    int lane = threadIdx.x & 31;
    int b = row >> 12, nk = (row >> 8) & 15, i = row & 255;
    float4 xv = *(const float4*)&know[(size_t)nk * 128 + lane * 4];
    float4 yv = *(const float4*)&g_O4[(size_t)row * 128 + lane * 4];
    float v0 = xv.x + yv.x, v1 = xv.y + yv.y, v2 = xv.z + yv.z, v3 = xv.w + yv.w;
    float mean = warp_sum(v0 + v1 + v2 + v3) * (1.f / 128.f);
    float d0 = v0 - mean, d1 = v1 - mean, d2 = v2 - mean, d3 = v3 - mean;
    float rstd = rsqrtf(warp_sum(d0*d0 + d1*d1 + d2*d2 + d3*d3) * (1.f/128.f) + 1e-5f);
    float4 gv = *(const float4*)&g[lane * 4];
    float4 bv = *(const float4*)&bb[lane * 4];
    *(float4*)&z[((size_t)(b * 256 + i) * 2048) + nk * 128 + lane * 4] =
        make_float4(d0*rstd*gv.x + bv.x, d1*rstd*gv.y + bv.y,
                    d2*rstd*gv.z + bv.z, d3*rstd*gv.w + bv.w);
}

extern "C" void kernel_launch(void* const* d_in, const int* in_sizes, int n_in,
                              void* d_out, int out_size) {
    const float* q_emb = (const float*)d_in[0];
    const float* s_emb = (const float*)d_in[1];
    const float* b1_Wq = (const float*)d_in[3];
    const float* b1_bq = (const float*)d_in[4];
    const float* b1_Wv = (const float*)d_in[5];
    const float* b1_bv = (const float*)d_in[6];
    const float* b1_Wo = (const float*)d_in[7];
    const float* b1_bo = (const float*)d_in[8];
    const float* b1_g  = (const float*)d_in[9];
    const float* b1_lng = (const float*)d_in[10];
    const float* b1_lnb = (const float*)d_in[11];
    const float* b4_Wq = (const float*)d_in[12];
    const float* b4_bq = (const float*)d_in[13];
    const float* b4_Wk = (const float*)d_in[14];
    const float* b4_bk = (const float*)d_in[15];
    const float* b4_Wv = (const float*)d_in[16];
    const float* b4_bv = (const float*)d_in[17];
    const float* b4_Wo = (const float*)d_in[18];
    const float* b4_bo = (const float*)d_in[19];
    const float* b4_g  = (const float*)d_in[20];
    const float* b4_lng = (const float*)d_in[21];
    const float* b4_lnb = (const float*)d_in[22];
    const float* know  = (const float*)d_in[23];
    float* z  = (float*)d_out;
    float* qs = z + 2097152;
    float* ks = z + 4194304;

    float *P1q, *P1v, *AO1, *O1, *p, *Q4, *K4, *V4, *AO4, *O4;
    cudaGetSymbolAddress((void**)&P1q, g_P1q);
    cudaGetSymbolAddress((void**)&P1v, g_P1v);
    cudaGetSymbolAddress((void**)&AO1, g_AO1);
    cudaGetSymbolAddress((void**)&O1,  g_O1);
    cudaGetSymbolAddress((void**)&p,   g_p);
    cudaGetSymbolAddress((void**)&Q4,  g_Q4);
    cudaGetSymbolAddress((void**)&K4,  g_K4);
    cudaGetSymbolAddress((void**)&V4,  g_V4);
    cudaGetSymbolAddress((void**)&AO4, g_AO4);
    cudaGetSymbolAddress((void**)&O4,  g_O4);

    cudaFuncSetAttribute(attn1_kernel, cudaFuncAttributeMaxDynamicSharedMemorySize, 49152);

    // 1. block1 Q/K projection (shared) + V projection
    gemm_kernel<<<dim3(32, 2, 2), 256>>>(q_emb, b1_Wq, b1_bq, P1q, 1024,
                                         s_emb, b1_Wv, b1_bv, P1v, 1024);
    // 2. block1 attention
    attn1_kernel<<<256, 256, 49152>>>(b1_g, qs);
    // 3. O1 projection
    gemm_kernel<<<dim3(32, 2, 1), 256>>>(AO1, b1_Wo, b1_bo, O1, 1024,
                                         AO1, b1_Wo, b1_bo, O1, 1024);
    // 4. p = LN(q_emb + O1)
    ln_res_kernel<<<128, 256>>>(q_emb, b1_lng, b1_lnb);
    // 5. block4 K/V projections
    gemm_kernel<<<dim3(32, 2, 2), 256>>>(q_emb, b4_Wk, b4_bk, K4, 1024,
                                         p,     b4_Wv, b4_bv, V4, 1024);
    // 5b. Q4 projection (16 rows)
    gemm_kernel<<<dim3(1, 2, 1), 256>>>(know, b4_Wq, b4_bq, Q4, 16,
                                        know, b4_Wq, b4_bq, Q4, 16);
    // 6. repack K4/V4
    repack_kernel<<<512, 256>>>();
    // 7. block4 attention
    attn4_kernel<<<512, 256>>>(b4_g, ks);
    // 8. O4 projection (16384 rows)
    gemm_kernel<<<dim3(512, 2, 1), 256>>>(AO4, b4_Wo, b4_bo, O4, 16384,
                                          AO4, b4_Wo, b4_bo, O4, 16384);
    // 9. z = LN(know + O4), scattered
    ln4_kernel<<<2048, 256>>>(know, b4_lng, b4_lnb, z);
}

// round 9
// speedup vs baseline: 1.1808x; 1.1808x over previous
#include <cuda_runtime.h>

#define FULLMASK 0xffffffffu

__device__ __forceinline__ float warp_sum(float v) {
#pragma unroll
    for (int o = 16; o; o >>= 1) v += __shfl_xor_sync(FULLMASK, v, o);
    return v;
}
__device__ __forceinline__ float warp_max(float v) {
#pragma unroll
    for (int o = 16; o; o >>= 1) v = fmaxf(v, __shfl_xor_sync(FULLMASK, v, o));
    return v;
}

// Transpose-reduce: in: acc[16] per lane (sum over lanes wanted per element).
// out: every lane returns the full 32-lane sum of element d=(lane>>1)&15;
// even lanes are the canonical writers. 16 shuffles total.
__device__ __forceinline__ float xreduce16(const float acc[16], int lane) {
    float b8[8];
#pragma unroll
    for (int i = 0; i < 8; i++) {
        float send = (lane & 16) ? acc[i] : acc[i + 8];
        float recv = __shfl_xor_sync(FULLMASK, send, 16);
        b8[i] = ((lane & 16) ? acc[i + 8] : acc[i]) + recv;
    }
    float b4[4];
#pragma unroll
    for (int i = 0; i < 4; i++) {
        float send = (lane & 8) ? b8[i] : b8[i + 4];
        float recv = __shfl_xor_sync(FULLMASK, send, 8);
        b4[i] = ((lane & 8) ? b8[i + 4] : b8[i]) + recv;
    }
    float b2[2];
#pragma unroll
    for (int i = 0; i < 2; i++) {
        float send = (lane & 4) ? b4[i] : b4[i + 2];
        float recv = __shfl_xor_sync(FULLMASK, send, 4);
        b2[i] = ((lane & 4) ? b4[i + 2] : b4[i]) + recv;
    }
    float send = (lane & 2) ? b2[0] : b2[1];
    float recv = __shfl_xor_sync(FULLMASK, send, 2);
    float v = ((lane & 2) ? b2[1] : b2[0]) + recv;
    v += __shfl_xor_sync(FULLMASK, v, 1);
    return v;
}

// ---------------- static scratch ----------------
__device__ __align__(16) float g_P1q[1024 * 128];
__device__ __align__(16) float g_P1v[1024 * 128];
__device__ __align__(16) float g_AO1[1024 * 128];
__device__ __align__(16) float g_p[1024 * 128];
__device__ __align__(16) float g_K4t[1024 * 128];   // (B,H,DK,S)
__device__ __align__(16) float g_V4bh[1024 * 128];  // (B,H,S,DK)
__device__ __align__(16) float g_AO4[16384 * 128];

// ================== GEMM core: tile 64 rows x 128 cols, 256 threads ==========
// acc[8][4]: thread (rg=t>>5, cg=t&31) owns rows rg*8..+7, cols cg*4..+3.
// Warp rg holds complete rows -> LN can stay warp-local.
// As: k-major, pad 65 (conflict-free ST + broadcast LD).
// Ws: k-major 32x128 (conflict-free ST + conflict-free float4 LD).
__device__ __forceinline__ void gcore(const float* __restrict__ A,
                                      const float* __restrict__ W,
                                      int row0, float acc[8][4],
                                      float* As, float* Ws) {
    const int t = threadIdx.x;
    const int rg = t >> 5, cg = t & 31;
    const int lr = t >> 2, lk = (t & 3) * 8;
    const int wc = t & 127, kh = (t >> 7) * 16;
#pragma unroll
    for (int r = 0; r < 8; r++) { acc[r][0] = acc[r][1] = acc[r][2] = acc[r][3] = 0.f; }
    for (int kb = 0; kb < 128; kb += 32) {
        float4 a0 = *(const float4*)&A[(size_t)(row0 + lr) * 128 + kb + lk];
        float4 a1 = *(const float4*)&A[(size_t)(row0 + lr) * 128 + kb + lk + 4];
        As[(lk + 0) * 65 + lr] = a0.x; As[(lk + 1) * 65 + lr] = a0.y;
        As[(lk + 2) * 65 + lr] = a0.z; As[(lk + 3) * 65 + lr] = a0.w;
        As[(lk + 4) * 65 + lr] = a1.x; As[(lk + 5) * 65 + lr] = a1.y;
        As[(lk + 6) * 65 + lr] = a1.z; As[(lk + 7) * 65 + lr] = a1.w;
#pragma unroll
        for (int q = 0; q < 4; q++) {
            float4 wv = *(const float4*)&W[(size_t)wc * 128 + kb + kh + q * 4];
            Ws[(kh + q * 4 + 0) * 128 + wc] = wv.x;
            Ws[(kh + q * 4 + 1) * 128 + wc] = wv.y;
            Ws[(kh + q * 4 + 2) * 128 + wc] = wv.z;
            Ws[(kh + q * 4 + 3) * 128 + wc] = wv.w;
        }
        __syncthreads();
#pragma unroll
        for (int k = 0; k < 32; k++) {
            float4 wv = *(const float4*)&Ws[k * 128 + cg * 4];
#pragma unroll
            for (int r = 0; r < 8; r++) {
                float a = As[k * 65 + rg * 8 + r];
                acc[r][0] += a * wv.x; acc[r][1] += a * wv.y;
                acc[r][2] += a * wv.z; acc[r][3] += a * wv.w;
            }
        }
        __syncthreads();
    }
}

// ---- plain dual GEMM: C = A @ W^T + b (two independent problems via z)
__global__ __launch_bounds__(256) void gemm_plain_dual(
    const float* A0, const float* W0, const float* B0, float* C0,
    const float* A1, const float* W1, const float* B1, float* C1) {
    __shared__ float As[32 * 65];
    __shared__ __align__(16) float Ws[32 * 128];
    const float *A, *W, *Bv; float* C;
    if (blockIdx.z == 0) { A = A0; W = W0; Bv = B0; C = C0; }
    else                 { A = A1; W = W1; Bv = B1; C = C1; }
    const int t = threadIdx.x, rg = t >> 5, cg = t & 31;
    const int row0 = blockIdx.x * 64;
    float acc[8][4];
    gcore(A, W, row0, acc, As, Ws);
    float4 bv = *(const float4*)&Bv[cg * 4];
#pragma unroll
    for (int r = 0; r < 8; r++) {
        int row = row0 + rg * 8 + r;
        *(float4*)&C[(size_t)row * 128 + cg * 4] =
            make_float4(acc[r][0] + bv.x, acc[r][1] + bv.y,
                        acc[r][2] + bv.z, acc[r][3] + bv.w);
    }
}

// ---- O1 GEMM + residual(q_emb) + LayerNorm -> g_p
__global__ __launch_bounds__(256) void gemm_lnres(
    const float* __restrict__ A, const float* __restrict__ W,
    const float* __restrict__ Bv, const float* __restrict__ X,
    const float* __restrict__ lng, const float* __restrict__ lnb,
    float* __restrict__ OUT) {
    __shared__ float As[32 * 65];
    __shared__ __align__(16) float Ws[32 * 128];
    const int t = threadIdx.x, rg = t >> 5, cg = t & 31, lane = t & 31;
    const int row0 = blockIdx.x * 64;
    float acc[8][4];
    gcore(A, W, row0, acc, As, Ws);
    float4 bv = *(const float4*)&Bv[cg * 4];
    float4 gv = *(const float4*)&lng[cg * 4];
    float4 bb = *(const float4*)&lnb[cg * 4];
#pragma unroll
    for (int r = 0; r < 8; r++) {
        int row = row0 + rg * 8 + r;
        float4 xv = *(const float4*)&X[(size_t)row * 128 + cg * 4];
        float v0 = acc[r][0] + bv.x + xv.x, v1 = acc[r][1] + bv.y + xv.y;
        float v2 = acc[r][2] + bv.z + xv.z, v3 = acc[r][3] + bv.w + xv.w;
        float s1 = warp_sum(v0 + v1 + v2 + v3);
        float s2 = warp_sum(v0 * v0 + v1 * v1 + v2 * v2 + v3 * v3);
        float mean = s1 * (1.f / 128.f);
        float var = s2 * (1.f / 128.f) - mean * mean;
        float rstd = rsqrtf(var + 1e-5f);
        (void)lane;
        *(float4*)&OUT[(size_t)row * 128 + cg * 4] =
            make_float4((v0 - mean) * rstd * gv.x + bb.x, (v1 - mean) * rstd * gv.y + bb.y,
                        (v2 - mean) * rstd * gv.z + bb.z, (v3 - mean) * rstd * gv.w + bb.w);
    }
}

// ---- KV4 dual GEMM with transposed epilogues (replaces repack):
// z=0: K = q_emb@Wk^T+bk  -> K4t[(b,h,dk,j)];  z=1: V = p@Wv^T+bv -> V4bh[(b,h,j,dk)]
__global__ __launch_bounds__(256) void gemm_kv(
    const float* A0, const float* W0, const float* B0,
    const float* A1, const float* W1, const float* B1) {
    __shared__ float As[32 * 65];
    __shared__ __align__(16) float Ws[32 * 128];
    const float *A, *W, *Bv;
    int zz = blockIdx.z;
    if (zz == 0) { A = A0; W = W0; Bv = B0; }
    else         { A = A1; W = W1; Bv = B1; }
    const int t = threadIdx.x, rg = t >> 5, cg = t & 31;
    const int row0 = blockIdx.x * 64;
    float acc[8][4];
    gcore(A, W, row0, acc, As, Ws);
    float4 bv = *(const float4*)&Bv[cg * 4];
#pragma unroll
    for (int r = 0; r < 8; r++) {
        int row = row0 + rg * 8 + r;
        int b = row >> 8, j = row & 255;
        float val[4] = {acc[r][0] + bv.x, acc[r][1] + bv.y,
                        acc[r][2] + bv.z, acc[r][3] + bv.w};
#pragma unroll
        for (int i = 0; i < 4; i++) {
            int c = cg * 4 + i;
            int h = c >> 4, dk = c & 15;
            if (zz == 0)
                g_K4t[((size_t)((b * 8 + h) * 16 + dk)) * 256 + j] = val[i];
            else
                g_V4bh[((size_t)((b * 8 + h) * 256 + j)) * 16 + dk] = val[i];
        }
    }
}

// ---- O4 GEMM + residual(know[nk]) + LayerNorm -> z (scattered)
__global__ __launch_bounds__(256) void gemm_lnz(
    const float* __restrict__ A, const float* __restrict__ W,
    const float* __restrict__ Bv, const float* __restrict__ know,
    const float* __restrict__ lng, const float* __restrict__ lnb,
    float* __restrict__ z) {
    __shared__ float As[32 * 65];
    __shared__ __align__(16) float Ws[32 * 128];
    const int t = threadIdx.x, rg = t >> 5, cg = t & 31;
    const int row0 = blockIdx.x * 64;
    float acc[8][4];
    gcore(A, W, row0, acc, As, Ws);
    float4 bv = *(const float4*)&Bv[cg * 4];
    float4 gv = *(const float4*)&lng[cg * 4];
    float4 bb = *(const float4*)&lnb[cg * 4];
#pragma unroll
    for (int r = 0; r < 8; r++) {
        int row = row0 + rg * 8 + r;          // (b*16+nk)*256 + si
        int b = row >> 12, nk = (row >> 8) & 15, si = row & 255;
        float4 xv = *(const float4*)&know[(size_t)nk * 128 + cg * 4];
        float v0 = acc[r][0] + bv.x + xv.x, v1 = acc[r][1] + bv.y + xv.y;
        float v2 = acc[r][2] + bv.z + xv.z, v3 = acc[r][3] + bv.w + xv.w;
        float s1 = warp_sum(v0 + v1 + v2 + v3);
        float s2 = warp_sum(v0 * v0 + v1 * v1 + v2 * v2 + v3 * v3);
        float mean = s1 * (1.f / 128.f);
        float var = s2 * (1.f / 128.f) - mean * mean;
        float rstd = rsqrtf(var + 1e-5f);
        *(float4*)&z[((size_t)(b * 256 + si) * 2048) + nk * 128 + cg * 4] =
            make_float4((v0 - mean) * rstd * gv.x + bb.x, (v1 - mean) * rstd * gv.y + bb.y,
                        (v2 - mean) * rstd * gv.z + bb.z, (v3 - mean) * rstd * gv.w + bb.w);
    }
}

// ---- block1 attention (peek_cur=True, maxout=False). grid 256 = B*H*8chunks.
__global__ __launch_bounds__(256) void attn1_kernel(
    const float* __restrict__ gamma, float* __restrict__ qscore) {
    extern __shared__ __align__(16) float dyn[];
    float* Ks = dyn;                 // 256*20
    float* Vs = dyn + 5120;          // 256*20
    float* rowbuf = dyn + 10240;     // 8*256
    const int bx = blockIdx.x;
    const int chunk = bx & 7, h = (bx >> 3) & 7, b = bx >> 6;
    const int t = threadIdx.x, lane = t & 31, w = t >> 5;
    {
        const float* ksrc = g_P1q + ((size_t)(b * 256 + t)) * 128 + h * 16;
        const float* vsrc = g_P1v + ((size_t)(b * 256 + t)) * 128 + h * 16;
#pragma unroll
        for (int c = 0; c < 4; c++) {
            *(float4*)&Ks[t * 20 + c * 4] = *(const float4*)&ksrc[c * 4];
            *(float4*)&Vs[t * 20 + c * 4] = *(const float4*)&vsrc[c * 4];
        }
    }
    __syncthreads();
    const float ag = fabsf(gamma[h]);
    float* myrow = rowbuf + w * 256;
    for (int it = 0; it < 4; it++) {
        const int i = chunk * 32 + it * 8 + w;
        float q[16];
#pragma unroll
        for (int c = 0; c < 4; c++) {
            float4 qv = *(const float4*)&Ks[i * 20 + c * 4];
            q[c * 4] = qv.x; q[c * 4 + 1] = qv.y; q[c * 4 + 2] = qv.z; q[c * 4 + 3] = qv.w;
        }
        float sc[8], m1 = -3.0e38f;
#pragma unroll
        for (int u = 0; u < 8; u++) {
            int j = lane + 32 * u;
            float s = 0.f;
#pragma unroll
            for (int c = 0; c < 4; c++) {
                float4 kv = *(const float4*)&Ks[j * 20 + c * 4];
                s += q[c*4]*kv.x + q[c*4+1]*kv.y + q[c*4+2]*kv.z + q[c*4+3]*kv.w;
            }
            sc[u] = s * 0.25f;
            if (j <= i) m1 = fmaxf(m1, sc[u]);
        }
        m1 = warp_max(m1);
        float lsum = 0.f;
#pragma unroll
        for (int u = 0; u < 8; u++) {
            int j = lane + 32 * u;
            lsum += (j <= i) ? __expf(sc[u] - m1) : 0.f;
            myrow[j] = sc[u];
        }
        float inv1 = 1.f / warp_sum(lsum);
        __syncwarp();
        // blocked phase: lane owns j in [8*lane, 8*lane+8)
        float scb[8], eb[8], cpref[8], run = 0.f;
#pragma unroll
        for (int o = 0; o < 8; o++) {
            int j = lane * 8 + o;
            scb[o] = myrow[j];
            eb[o] = (j <= i) ? __expf(scb[o] - m1) : 0.f;
            run += eb[o]; cpref[o] = run;
        }
        float x = run;
#pragma unroll
        for (int d = 1; d < 32; d <<= 1) {
            float n = __shfl_up_sync(FULLMASK, x, d);
            if (lane >= d) x += n;
        }
        float excl = x - run;
        float s2[8], m2 = -3.0e38f;
#pragma unroll
        for (int o = 0; o < 8; o++) {
            int j = lane * 8 + o;
            bool valid = (j <= i);
            float c = (cpref[o] + excl) * inv1;
            float pos = valid ? (float)(i - j) : 0.f;
            float dist = sqrtf(fmaxf(1.f - c, 0.f) * pos);
            float eff = fmaxf(__expf(-ag * dist), 1e-5f);
            s2[o] = valid ? scb[o] * eff : -3.0e38f;
            m2 = fmaxf(m2, s2[o]);
        }
        m2 = warp_max(m2);
        float ww[8], ls = 0.f;
#pragma unroll
        for (int o = 0; o < 8; o++) { ww[o] = __expf(s2[o] - m2); ls += ww[o]; }
        float inv2 = 1.f / warp_sum(ls);
        float p[8];
#pragma unroll
        for (int o = 0; o < 8; o++) p[o] = ww[o] * inv2;
        float* qrow = qscore + ((size_t)((b * 8 + h) * 256 + i)) * 256;
        *(float4*)&qrow[lane * 8] = make_float4(p[0], p[1], p[2], p[3]);
        *(float4*)&qrow[lane * 8 + 4] = make_float4(p[4], p[5], p[6], p[7]);
        __syncwarp();
#pragma unroll
        for (int o = 0; o < 8; o++) myrow[lane * 8 + o] = p[o];
        __syncwarp();
        float acc[16];
#pragma unroll
        for (int d = 0; d < 16; d++) acc[d] = 0.f;
#pragma unroll
        for (int u = 0; u < 8; u++) {
            int j = lane + 32 * u;
            float pv = myrow[j];
#pragma unroll
            for (int c = 0; c < 4; c++) {
                float4 vv = *(const float4*)&Vs[j * 20 + c * 4];
                acc[c*4] += pv*vv.x; acc[c*4+1] += pv*vv.y;
                acc[c*4+2] += pv*vv.z; acc[c*4+3] += pv*vv.w;
            }
        }
        float v = xreduce16(acc, lane);
        if (!(lane & 1))
            g_AO1[((size_t)(b * 256 + i)) * 128 + h * 16 + (lane >> 1)] = v;
        __syncwarp();
    }
}

// ---- block4 attention (peek_cur=False, maxout=True). Row-invariant scores.
// Q4 computed inline from know @ Wq^T + bq (head slice h).
__global__ __launch_bounds__(256) void attn4_kernel(
    const float* __restrict__ gamma, float* __restrict__ kscore,
    const float* __restrict__ know, const float* __restrict__ Wq,
    const float* __restrict__ bq) {
    __shared__ __align__(16) float Vs[256 * 20];
    __shared__ float sc[256];
    __shared__ float qs[16];
    __shared__ float red[8];
    __shared__ float P[257];
    const int bx = blockIdx.x;
    const int h = bx & 7, nk = (bx >> 3) & 15, b = bx >> 7;
    const int t = threadIdx.x, lane = t & 31, w = t >> 5;
    // inline Q4: warp w computes dk = 2w, 2w+1
#pragma unroll
    for (int s = 0; s < 2; s++) {
        int dk = w * 2 + s;
        const float* wr = Wq + (size_t)(h * 16 + dk) * 128;
        float4 wv = *(const float4*)&wr[lane * 4];
        float4 kn = *(const float4*)&know[(size_t)nk * 128 + lane * 4];
        float part = wv.x * kn.x + wv.y * kn.y + wv.z * kn.z + wv.w * kn.w;
        float tot = warp_sum(part);
        if (lane == 0) qs[dk] = tot + bq[h * 16 + dk];
    }
    __syncthreads();
    {
        const float* kb = g_K4t + ((size_t)((b * 8 + h) * 16)) * 256;
        float s = 0.f;
#pragma unroll
        for (int dk = 0; dk < 16; dk++) s += qs[dk] * kb[dk * 256 + t];
        sc[t] = s * 0.25f;
        const float* vsrc = g_V4bh + ((size_t)((b * 8 + h) * 256 + t)) * 16;
#pragma unroll
        for (int c = 0; c < 4; c++)
            *(float4*)&Vs[t * 20 + c * 4] = *(const float4*)&vsrc[c * 4];
    }
    __syncthreads();
    float myv = sc[t];
    float wm = warp_max(myv);
    if (lane == 0) red[w] = wm;
    __syncthreads();
    float M = red[0];
#pragma unroll
    for (int k = 1; k < 8; k++) M = fmaxf(M, red[k]);
    float e = __expf(myv - M);
    float v = e;
#pragma unroll
    for (int d = 1; d < 32; d <<= 1) {
        float n = __shfl_up_sync(FULLMASK, v, d);
        if (lane >= d) v += n;
    }
    __syncthreads();
    if (lane == 31) red[w] = v;
    __syncthreads();
    float off = 0.f;
    for (int k = 0; k < w; k++) off += red[k];
    P[t + 1] = v + off;
    if (t == 0) P[0] = 0.f;
    __syncthreads();
    const float ag = fabsf(gamma[h]);
    float* ksbase = kscore + ((size_t)(b * 8 + h)) * 1048576 + (size_t)nk * 256;
    for (int i = w; i < 256; i += 8) {
        float p[8];
        if (i == 0) {
#pragma unroll
            for (int u = 0; u < 8; u++) p[u] = 0.f;
        } else {
            float Ei = P[i], invE = 1.f / Ei;
            float s2[8], m2 = -3.0e38f;
#pragma unroll
            for (int u = 0; u < 8; u++) {
                int j = lane + 32 * u;
                bool valid = (j < i);
                float r = fmaxf((Ei - P[j + 1]) * invE, 0.f);
                float pos = valid ? (float)(i - j) : 0.f;
                float dist = sqrtf(r * pos);
                float eff = fmaxf(__expf(-ag * dist), 1e-5f);
                s2[u] = valid ? sc[j] * eff : -3.0e38f;
                m2 = fmaxf(m2, s2[u]);
            }
            m2 = warp_max(m2);
            float ls = 0.f, ww[8];
#pragma unroll
            for (int u = 0; u < 8; u++) { ww[u] = __expf(s2[u] - m2); ls += ww[u]; }
            float sum2 = warp_sum(ls);
            float f = fminf(sum2, 5.f) / sum2;   // maxout folded in
#pragma unroll
            for (int u = 0; u < 8; u++) p[u] = ww[u] * f;
        }
        float* krow = ksbase + (size_t)i * 4096;
#pragma unroll
        for (int u = 0; u < 8; u++) krow[lane + 32 * u] = p[u];
        float acc[16];
#pragma unroll
        for (int d = 0; d < 16; d++) acc[d] = 0.f;
#pragma unroll
        for (int u = 0; u < 8; u++) {
            int j = lane + 32 * u;
            float pv = p[u];
#pragma unroll
            for (int c = 0; c < 4; c++) {
                float4 vv = *(const float4*)&Vs[j * 20 + c * 4];
                acc[c*4] += pv*vv.x; acc[c*4+1] += pv*vv.y;
                acc[c*4+2] += pv*vv.z; acc[c*4+3] += pv*vv.w;
            }
        }
        float vr = xreduce16(acc, lane);
        if (!(lane & 1))
            g_AO4[((size_t)((b * 16 + nk) * 256 + i)) * 128 + h * 16 + (lane >> 1)] = vr;
    }
}

extern "C" void kernel_launch(void* const* d_in, const int* in_sizes, int n_in,
                              void* d_out, int out_size) {
    const float* q_emb = (const float*)d_in[0];
    const float* s_emb = (const float*)d_in[1];
    const float* b1_Wq = (const float*)d_in[3];
    const float* b1_bq = (const float*)d_in[4];
    const float* b1_Wv = (const float*)d_in[5];
    const float* b1_bv = (const float*)d_in[6];
    const float* b1_Wo = (const float*)d_in[7];
    const float* b1_bo = (const float*)d_in[8];
    const float* b1_g  = (const float*)d_in[9];
    const float* b1_lng = (const float*)d_in[10];
    const float* b1_lnb = (const float*)d_in[11];
    const float* b4_Wq = (const float*)d_in[12];
    const float* b4_bq = (const float*)d_in[13];
    const float* b4_Wk = (const float*)d_in[14];
    const float* b4_bk = (const float*)d_in[15];
    const float* b4_Wv = (const float*)d_in[16];
    const float* b4_bv = (const float*)d_in[17];
    const float* b4_Wo = (const float*)d_in[18];
    const float* b4_bo = (const float*)d_in[19];
    const float* b4_g  = (const float*)d_in[20];
    const float* b4_lng = (const float*)d_in[21];
    const float* b4_lnb = (const float*)d_in[22];
    const float* know  = (const float*)d_in[23];
    float* z  = (float*)d_out;
    float* qs = z + 2097152;
    float* ks = z + 4194304;

    float *P1q, *P1v, *AO1, *p, *AO4;
    cudaGetSymbolAddress((void**)&P1q, g_P1q);
    cudaGetSymbolAddress((void**)&P1v, g_P1v);
    cudaGetSymbolAddress((void**)&AO1, g_AO1);
    cudaGetSymbolAddress((void**)&p,   g_p);
    cudaGetSymbolAddress((void**)&AO4, g_AO4);

    cudaFuncSetAttribute(attn1_kernel, cudaFuncAttributeMaxDynamicSharedMemorySize, 49152);

    // 1. block1 Q/K (shared W) + V projections
    gemm_plain_dual<<<dim3(16, 1, 2), 256>>>(q_emb, b1_Wq, b1_bq, P1q,
                                             s_emb, b1_Wv, b1_bv, P1v);
    // 2. block1 attention -> qs + AO1
    attn1_kernel<<<256, 256, 49152>>>(b1_g, qs);
    // 3. O1 GEMM + residual + LN -> p
    gemm_lnres<<<16, 256>>>(AO1, b1_Wo, b1_bo, q_emb, b1_lng, b1_lnb, p);
    // 4. block4 K/V projections with transposed epilogue -> K4t / V4bh
    gemm_kv<<<dim3(16, 1, 2), 256>>>(q_emb, b4_Wk, b4_bk,
                                     p,     b4_Wv, b4_bv);
    // 5. block4 attention (inline Q4) -> ks + AO4
    attn4_kernel<<<512, 256>>>(b4_g, ks, know, b4_Wq, b4_bq);
    // 6. O4 GEMM + residual(know) + LN -> z (scattered)
    gemm_lnz<<<256, 256>>>(AO4, b4_Wo, b4_bo, know, b4_lng, b4_lnb, z);
}

// round 10
// speedup vs baseline: 1.2805x; 1.0844x over previous
#include <cuda_runtime.h>

#define FULLMASK 0xffffffffu

__device__ __forceinline__ float warp_sum(float v) {
#pragma unroll
    for (int o = 16; o; o >>= 1) v += __shfl_xor_sync(FULLMASK, v, o);
    return v;
}
__device__ __forceinline__ float warp_max(float v) {
#pragma unroll
    for (int o = 16; o; o >>= 1) v = fmaxf(v, __shfl_xor_sync(FULLMASK, v, o));
    return v;
}

// Transpose-reduce: acc[16] per lane -> full 32-lane sum of element (lane>>1)&15
// on every lane; even lanes are canonical writers. 16 shuffles.
__device__ __forceinline__ float xreduce16(const float acc[16], int lane) {
    float b8[8];
#pragma unroll
    for (int i = 0; i < 8; i++) {
        float send = (lane & 16) ? acc[i] : acc[i + 8];
        float recv = __shfl_xor_sync(FULLMASK, send, 16);
        b8[i] = ((lane & 16) ? acc[i + 8] : acc[i]) + recv;
    }
    float b4[4];
#pragma unroll
    for (int i = 0; i < 4; i++) {
        float send = (lane & 8) ? b8[i] : b8[i + 4];
        float recv = __shfl_xor_sync(FULLMASK, send, 8);
        b4[i] = ((lane & 8) ? b8[i + 4] : b8[i]) + recv;
    }
    float b2[2];
#pragma unroll
    for (int i = 0; i < 2; i++) {
        float send = (lane & 4) ? b4[i] : b4[i + 2];
        float recv = __shfl_xor_sync(FULLMASK, send, 4);
        b2[i] = ((lane & 4) ? b4[i + 2] : b4[i]) + recv;
    }
    float send = (lane & 2) ? b2[0] : b2[1];
    float recv = __shfl_xor_sync(FULLMASK, send, 2);
    float v = ((lane & 2) ? b2[1] : b2[0]) + recv;
    v += __shfl_xor_sync(FULLMASK, v, 1);
    return v;
}

// ---------------- static scratch ----------------
__device__ __align__(16) float g_P1q[1024 * 128];
__device__ __align__(16) float g_P1v[1024 * 128];
__device__ __align__(16) float g_AO1[1024 * 128];
__device__ __align__(16) float g_K4t[1024 * 128];   // (B,H,DK,S)
__device__ __align__(16) float g_V4bh[1024 * 128];  // (B,H,S,DK)
__device__ __align__(16) float g_AO4[16384 * 128];

// ========== 16-row GEMM core: tile 16 x 128, 256 threads, acc[2][4] ==========
// warp rg owns rows rg*2, rg*2+1 (whole rows -> warp-local LN possible).
__device__ __forceinline__ void gcore16(const float* __restrict__ A,
                                        const float* __restrict__ W,
                                        int row0, float acc[2][4],
                                        float* As /*32*17*/, float* Ws /*32*128*/) {
    const int t = threadIdx.x;
    const int rg = t >> 5, cg = t & 31;
    const int lr = t >> 4, lk2 = (t & 15) * 2;
    const int wc = t & 127, kh = (t >> 7) * 16;
#pragma unroll
    for (int r = 0; r < 2; r++) { acc[r][0] = acc[r][1] = acc[r][2] = acc[r][3] = 0.f; }
    for (int kb = 0; kb < 128; kb += 32) {
        float2 a = *(const float2*)&A[(size_t)(row0 + lr) * 128 + kb + lk2];
        As[lk2 * 17 + lr] = a.x;
        As[(lk2 + 1) * 17 + lr] = a.y;
#pragma unroll
        for (int q = 0; q < 4; q++) {
            float4 wv = *(const float4*)&W[(size_t)wc * 128 + kb + kh + q * 4];
            Ws[(kh + q * 4 + 0) * 128 + wc] = wv.x;
            Ws[(kh + q * 4 + 1) * 128 + wc] = wv.y;
            Ws[(kh + q * 4 + 2) * 128 + wc] = wv.z;
            Ws[(kh + q * 4 + 3) * 128 + wc] = wv.w;
        }
        __syncthreads();
#pragma unroll
        for (int k = 0; k < 32; k++) {
            float4 wv = *(const float4*)&Ws[k * 128 + cg * 4];
#pragma unroll
            for (int r = 0; r < 2; r++) {
                float a2 = As[k * 17 + rg * 2 + r];
                acc[r][0] += a2 * wv.x; acc[r][1] += a2 * wv.y;
                acc[r][2] += a2 * wv.z; acc[r][3] += a2 * wv.w;
            }
        }
        __syncthreads();
    }
}

// ---- launch 1: three independent projections. z=0: P1q, z=1: P1v, z=2: K4t
__global__ __launch_bounds__(256) void k3gemm(
    const float* __restrict__ q_emb, const float* __restrict__ s_emb,
    const float* __restrict__ Wq1, const float* __restrict__ bq1,
    const float* __restrict__ Wv1, const float* __restrict__ bv1,
    const float* __restrict__ Wk4, const float* __restrict__ bk4) {
    __shared__ float As[32 * 17];
    __shared__ __align__(16) float Ws[32 * 128];
    const int z = blockIdx.z, row0 = blockIdx.x * 16;
    const int t = threadIdx.x, rg = t >> 5, cg = t & 31;
    const float *A, *W, *Bv;
    if (z == 0)      { A = q_emb; W = Wq1; Bv = bq1; }
    else if (z == 1) { A = s_emb; W = Wv1; Bv = bv1; }
    else             { A = q_emb; W = Wk4; Bv = bk4; }
    float acc[2][4];
    gcore16(A, W, row0, acc, As, Ws);
    float4 bv = *(const float4*)&Bv[cg * 4];
#pragma unroll
    for (int r = 0; r < 2; r++) {
        int row = row0 + rg * 2 + r;
        float v[4] = {acc[r][0] + bv.x, acc[r][1] + bv.y,
                      acc[r][2] + bv.z, acc[r][3] + bv.w};
        if (z == 0) {
            *(float4*)&g_P1q[(size_t)row * 128 + cg * 4] = make_float4(v[0], v[1], v[2], v[3]);
        } else if (z == 1) {
            *(float4*)&g_P1v[(size_t)row * 128 + cg * 4] = make_float4(v[0], v[1], v[2], v[3]);
        } else {
            int b = row >> 8, j = row & 255;
#pragma unroll
            for (int i = 0; i < 4; i++) {
                int c = cg * 4 + i, h = c >> 4, dk = c & 15;
                g_K4t[((size_t)((b * 8 + h) * 16 + dk)) * 256 + j] = v[i];
            }
        }
    }
}

// ---- launch 3: O1 GEMM + residual + LN -> p (smem only) -> V GEMM -> V4bh
__global__ __launch_bounds__(256) void fused_pv(
    const float* __restrict__ Wo1, const float* __restrict__ bo1,
    const float* __restrict__ q_emb,
    const float* __restrict__ lng, const float* __restrict__ lnb,
    const float* __restrict__ Wv4, const float* __restrict__ bv4) {
    __shared__ float As[32 * 17];
    __shared__ __align__(16) float Ws[32 * 128];
    __shared__ __align__(16) float Ps[16 * 128];
    const int t = threadIdx.x, rg = t >> 5, cg = t & 31;
    const int row0 = blockIdx.x * 16;
    float acc[2][4];
    gcore16(g_AO1, Wo1, row0, acc, As, Ws);
    {
        float4 bv = *(const float4*)&bo1[cg * 4];
        float4 gv = *(const float4*)&lng[cg * 4];
        float4 bb = *(const float4*)&lnb[cg * 4];
#pragma unroll
        for (int r = 0; r < 2; r++) {
            int row = row0 + rg * 2 + r;
            float4 xv = *(const float4*)&q_emb[(size_t)row * 128 + cg * 4];
            float v0 = acc[r][0] + bv.x + xv.x, v1 = acc[r][1] + bv.y + xv.y;
            float v2 = acc[r][2] + bv.z + xv.z, v3 = acc[r][3] + bv.w + xv.w;
            float s1 = warp_sum(v0 + v1 + v2 + v3);
            float s2 = warp_sum(v0 * v0 + v1 * v1 + v2 * v2 + v3 * v3);
            float mean = s1 * (1.f / 128.f);
            float var = s2 * (1.f / 128.f) - mean * mean;
            float rstd = rsqrtf(var + 1e-5f);
            *(float4*)&Ps[(rg * 2 + r) * 128 + cg * 4] =
                make_float4((v0 - mean) * rstd * gv.x + bb.x, (v1 - mean) * rstd * gv.y + bb.y,
                            (v2 - mean) * rstd * gv.z + bb.z, (v3 - mean) * rstd * gv.w + bb.w);
        }
    }
    __syncthreads();
    // second GEMM: V = Ps @ Wv4^T + bv4, transposed scatter to V4bh
    const int wc = t & 127, kh = (t >> 7) * 16;
    float vac[2][4];
#pragma unroll
    for (int r = 0; r < 2; r++) { vac[r][0] = vac[r][1] = vac[r][2] = vac[r][3] = 0.f; }
    for (int kb = 0; kb < 128; kb += 32) {
#pragma unroll
        for (int q = 0; q < 4; q++) {
            float4 wv = *(const float4*)&Wv4[(size_t)wc * 128 + kb + kh + q * 4];
            Ws[(kh + q * 4 + 0) * 128 + wc] = wv.x;
            Ws[(kh + q * 4 + 1) * 128 + wc] = wv.y;
            Ws[(kh + q * 4 + 2) * 128 + wc] = wv.z;
            Ws[(kh + q * 4 + 3) * 128 + wc] = wv.w;
        }
        __syncthreads();
#pragma unroll
        for (int k = 0; k < 32; k++) {
            float4 wv = *(const float4*)&Ws[k * 128 + cg * 4];
#pragma unroll
            for (int r = 0; r < 2; r++) {
                float a2 = Ps[(rg * 2 + r) * 128 + kb + k];
                vac[r][0] += a2 * wv.x; vac[r][1] += a2 * wv.y;
                vac[r][2] += a2 * wv.z; vac[r][3] += a2 * wv.w;
            }
        }
        __syncthreads();
    }
    float4 bv = *(const float4*)&bv4[cg * 4];
#pragma unroll
    for (int r = 0; r < 2; r++) {
        int row = row0 + rg * 2 + r;
        int b = row >> 8, j = row & 255;
        float v[4] = {vac[r][0] + bv.x, vac[r][1] + bv.y,
                      vac[r][2] + bv.z, vac[r][3] + bv.w};
#pragma unroll
        for (int i = 0; i < 4; i++) {
            int c = cg * 4 + i, h = c >> 4, dk = c & 15;
            g_V4bh[((size_t)((b * 8 + h) * 256 + j)) * 16 + dk] = v[i];
        }
    }
}

// ========== 64-row GEMM core (for the big O4 GEMM) ==========
__device__ __forceinline__ void gcore64(const float* __restrict__ A,
                                        const float* __restrict__ W,
                                        int row0, float acc[8][4],
                                        float* As, float* Ws) {
    const int t = threadIdx.x;
    const int rg = t >> 5, cg = t & 31;
    const int lr = t >> 2, lk = (t & 3) * 8;
    const int wc = t & 127, kh = (t >> 7) * 16;
#pragma unroll
    for (int r = 0; r < 8; r++) { acc[r][0] = acc[r][1] = acc[r][2] = acc[r][3] = 0.f; }
    for (int kb = 0; kb < 128; kb += 32) {
        float4 a0 = *(const float4*)&A[(size_t)(row0 + lr) * 128 + kb + lk];
        float4 a1 = *(const float4*)&A[(size_t)(row0 + lr) * 128 + kb + lk + 4];
        As[(lk + 0) * 65 + lr] = a0.x; As[(lk + 1) * 65 + lr] = a0.y;
        As[(lk + 2) * 65 + lr] = a0.z; As[(lk + 3) * 65 + lr] = a0.w;
        As[(lk + 4) * 65 + lr] = a1.x; As[(lk + 5) * 65 + lr] = a1.y;
        As[(lk + 6) * 65 + lr] = a1.z; As[(lk + 7) * 65 + lr] = a1.w;
#pragma unroll
        for (int q = 0; q < 4; q++) {
            float4 wv = *(const float4*)&W[(size_t)wc * 128 + kb + kh + q * 4];
            Ws[(kh + q * 4 + 0) * 128 + wc] = wv.x;
            Ws[(kh + q * 4 + 1) * 128 + wc] = wv.y;
            Ws[(kh + q * 4 + 2) * 128 + wc] = wv.z;
            Ws[(kh + q * 4 + 3) * 128 + wc] = wv.w;
        }
        __syncthreads();
#pragma unroll
        for (int k = 0; k < 32; k++) {
            float4 wv = *(const float4*)&Ws[k * 128 + cg * 4];
#pragma unroll
            for (int r = 0; r < 8; r++) {
                float a = As[k * 65 + rg * 8 + r];
                acc[r][0] += a * wv.x; acc[r][1] += a * wv.y;
                acc[r][2] += a * wv.z; acc[r][3] += a * wv.w;
            }
        }
        __syncthreads();
    }
}

// ---- launch 5: O4 GEMM + residual(know[nk]) + LN -> z (scattered)
__global__ __launch_bounds__(256) void gemm_lnz(
    const float* __restrict__ W, const float* __restrict__ Bv,
    const float* __restrict__ know,
    const float* __restrict__ lng, const float* __restrict__ lnb,
    float* __restrict__ z) {
    __shared__ float As[32 * 65];
    __shared__ __align__(16) float Ws[32 * 128];
    const int t = threadIdx.x, rg = t >> 5, cg = t & 31;
    const int row0 = blockIdx.x * 64;
    float acc[8][4];
    gcore64(g_AO4, W, row0, acc, As, Ws);
    float4 bv = *(const float4*)&Bv[cg * 4];
    float4 gv = *(const float4*)&lng[cg * 4];
    float4 bb = *(const float4*)&lnb[cg * 4];
#pragma unroll
    for (int r = 0; r < 8; r++) {
        int row = row0 + rg * 8 + r;          // (b*16+nk)*256 + si
        int b = row >> 12, nk = (row >> 8) & 15, si = row & 255;
        float4 xv = *(const float4*)&know[(size_t)nk * 128 + cg * 4];
        float v0 = acc[r][0] + bv.x + xv.x, v1 = acc[r][1] + bv.y + xv.y;
        float v2 = acc[r][2] + bv.z + xv.z, v3 = acc[r][3] + bv.w + xv.w;
        float s1 = warp_sum(v0 + v1 + v2 + v3);
        float s2 = warp_sum(v0 * v0 + v1 * v1 + v2 * v2 + v3 * v3);
        float mean = s1 * (1.f / 128.f);
        float var = s2 * (1.f / 128.f) - mean * mean;
        float rstd = rsqrtf(var + 1e-5f);
        *(float4*)&z[((size_t)(b * 256 + si) * 2048) + nk * 128 + cg * 4] =
            make_float4((v0 - mean) * rstd * gv.x + bb.x, (v1 - mean) * rstd * gv.y + bb.y,
                        (v2 - mean) * rstd * gv.z + bb.z, (v3 - mean) * rstd * gv.w + bb.w);
    }
}

// ---- block1 attention (peek_cur=True, maxout=False). grid 256 = B*H*8chunks.
// Triangular skip: within a block, j<=i possible only for u <= chunk.
__global__ __launch_bounds__(256) void attn1_kernel(
    const float* __restrict__ gamma, float* __restrict__ qscore) {
    extern __shared__ __align__(16) float dyn[];
    float* Ks = dyn;                 // 256*20
    float* Vs = dyn + 5120;          // 256*20
    float* rowbuf = dyn + 10240;     // 8*256
    const int bx = blockIdx.x;
    const int chunk = bx & 7, h = (bx >> 3) & 7, b = bx >> 6;
    const int t = threadIdx.x, lane = t & 31, w = t >> 5;
    {
        const float* ksrc = g_P1q + ((size_t)(b * 256 + t)) * 128 + h * 16;
        const float* vsrc = g_P1v + ((size_t)(b * 256 + t)) * 128 + h * 16;
#pragma unroll
        for (int c = 0; c < 4; c++) {
            *(float4*)&Ks[t * 20 + c * 4] = *(const float4*)&ksrc[c * 4];
            *(float4*)&Vs[t * 20 + c * 4] = *(const float4*)&vsrc[c * 4];
        }
    }
    __syncthreads();
    const float ag = fabsf(gamma[h]);
    float* myrow = rowbuf + w * 256;
    for (int it = 0; it < 4; it++) {
        const int i = chunk * 32 + it * 8 + w;
        float q[16];
#pragma unroll
        for (int c = 0; c < 4; c++) {
            float4 qv = *(const float4*)&Ks[i * 20 + c * 4];
            q[c * 4] = qv.x; q[c * 4 + 1] = qv.y; q[c * 4 + 2] = qv.z; q[c * 4 + 3] = qv.w;
        }
        float sc[8], m1 = -3.0e38f;
#pragma unroll
        for (int u = 0; u < 8; u++) {
            if (u <= chunk) {
                int j = lane + 32 * u;
                float s = 0.f;
#pragma unroll
                for (int c = 0; c < 4; c++) {
                    float4 kv = *(const float4*)&Ks[j * 20 + c * 4];
                    s += q[c*4]*kv.x + q[c*4+1]*kv.y + q[c*4+2]*kv.z + q[c*4+3]*kv.w;
                }
                sc[u] = s * 0.25f;
                if (j <= i) m1 = fmaxf(m1, sc[u]);
            }
        }
        m1 = warp_max(m1);
        float lsum = 0.f;
#pragma unroll
        for (int u = 0; u < 8; u++) {
            if (u <= chunk) {
                int j = lane + 32 * u;
                lsum += (j <= i) ? __expf(sc[u] - m1) : 0.f;
                myrow[j] = sc[u];
            }
        }
        float inv1 = 1.f / warp_sum(lsum);
        __syncwarp();
        // blocked phase: lane owns j in [8*lane, 8*lane+8)
        float scb[8], eb[8], cpref[8], run = 0.f;
#pragma unroll
        for (int o = 0; o < 8; o++) {
            int j = lane * 8 + o;
            scb[o] = myrow[j];
            eb[o] = (j <= i) ? __expf(scb[o] - m1) : 0.f;
            run += eb[o]; cpref[o] = run;
        }
        float x = run;
#pragma unroll
        for (int d = 1; d < 32; d <<= 1) {
            float n = __shfl_up_sync(FULLMASK, x, d);
            if (lane >= d) x += n;
        }
        float excl = x - run;
        float s2[8], m2 = -3.0e38f;
#pragma unroll
        for (int o = 0; o < 8; o++) {
            int j = lane * 8 + o;
            bool valid = (j <= i);
            float c = (cpref[o] + excl) * inv1;
            float pos = valid ? (float)(i - j) : 0.f;
            float dist = sqrtf(fmaxf(1.f - c, 0.f) * pos);
            float eff = fmaxf(__expf(-ag * dist), 1e-5f);
            s2[o] = valid ? scb[o] * eff : -3.0e38f;
            m2 = fmaxf(m2, s2[o]);
        }
        m2 = warp_max(m2);
        float ww[8], ls = 0.f;
#pragma unroll
        for (int o = 0; o < 8; o++) { ww[o] = __expf(s2[o] - m2); ls += ww[o]; }
        float inv2 = 1.f / warp_sum(ls);
        float p[8];
#pragma unroll
        for (int o = 0; o < 8; o++) p[o] = ww[o] * inv2;
        float* qrow = qscore + ((size_t)((b * 8 + h) * 256 + i)) * 256;
        *(float4*)&qrow[lane * 8] = make_float4(p[0], p[1], p[2], p[3]);
        *(float4*)&qrow[lane * 8 + 4] = make_float4(p[4], p[5], p[6], p[7]);
        __syncwarp();
#pragma unroll
        for (int o = 0; o < 8; o++) myrow[lane * 8 + o] = p[o];
        __syncwarp();
        float acc[16];
#pragma unroll
        for (int d = 0; d < 16; d++) acc[d] = 0.f;
#pragma unroll
        for (int u = 0; u < 8; u++) {
            if (u <= chunk) {
                int j = lane + 32 * u;
                float pv = myrow[j];
#pragma unroll
                for (int c = 0; c < 4; c++) {
                    float4 vv = *(const float4*)&Vs[j * 20 + c * 4];
                    acc[c*4] += pv*vv.x; acc[c*4+1] += pv*vv.y;
                    acc[c*4+2] += pv*vv.z; acc[c*4+3] += pv*vv.w;
                }
            }
        }
        float v = xreduce16(acc, lane);
        if (!(lane & 1))
            g_AO1[((size_t)(b * 256 + i)) * 128 + h * 16 + (lane >> 1)] = v;
        __syncwarp();
    }
}

// ---- block4 attention (peek_cur=False, maxout=True). Row-invariant scores.
// Triangular skip: for row i, j<i possible only when 32u < i (warp-uniform).
__global__ __launch_bounds__(256) void attn4_kernel(
    const float* __restrict__ gamma, float* __restrict__ kscore,
    const float* __restrict__ know, const float* __restrict__ Wq,
    const float* __restrict__ bq) {
    __shared__ __align__(16) float Vs[256 * 20];
    __shared__ float sc[256];
    __shared__ float qs[16];
    __shared__ float red[8];
    __shared__ float P[257];
    const int bx = blockIdx.x;
    const int h = bx & 7, nk = (bx >> 3) & 15, b = bx >> 7;
    const int t = threadIdx.x, lane = t & 31, w = t >> 5;
    // inline Q4: warp w computes dk = 2w, 2w+1
#pragma unroll
    for (int s = 0; s < 2; s++) {
        int dk = w * 2 + s;
        const float* wr = Wq + (size_t)(h * 16 + dk) * 128;
        float4 wv = *(const float4*)&wr[lane * 4];
        float4 kn = *(const float4*)&know[(size_t)nk * 128 + lane * 4];
        float part = wv.x * kn.x + wv.y * kn.y + wv.z * kn.z + wv.w * kn.w;
        float tot = warp_sum(part);
        if (lane == 0) qs[dk] = tot + bq[h * 16 + dk];
    }
    __syncthreads();
    {
        const float* kb = g_K4t + ((size_t)((b * 8 + h) * 16)) * 256;
        float s = 0.f;
#pragma unroll
        for (int dk = 0; dk < 16; dk++) s += qs[dk] * kb[dk * 256 + t];
        sc[t] = s * 0.25f;
        const float* vsrc = g_V4bh + ((size_t)((b * 8 + h) * 256 + t)) * 16;
#pragma unroll
        for (int c = 0; c < 4; c++)
            *(float4*)&Vs[t * 20 + c * 4] = *(const float4*)&vsrc[c * 4];
    }
    __syncthreads();
    float myv = sc[t];
    float wm = warp_max(myv);
    if (lane == 0) red[w] = wm;
    __syncthreads();
    float M = red[0];
#pragma unroll
    for (int k = 1; k < 8; k++) M = fmaxf(M, red[k]);
    float e = __expf(myv - M);
    float v = e;
#pragma unroll
    for (int d = 1; d < 32; d <<= 1) {
        float n = __shfl_up_sync(FULLMASK, v, d);
        if (lane >= d) v += n;
    }
    __syncthreads();
    if (lane == 31) red[w] = v;
    __syncthreads();
    float off = 0.f;
    for (int k = 0; k < w; k++) off += red[k];
    P[t + 1] = v + off;
    if (t == 0) P[0] = 0.f;
    __syncthreads();
    const float ag = fabsf(gamma[h]);
    float* ksbase = kscore + ((size_t)(b * 8 + h)) * 1048576 + (size_t)nk * 256;
    for (int i = w; i < 256; i += 8) {
        float p[8];
        if (i == 0) {
#pragma unroll
            for (int u = 0; u < 8; u++) p[u] = 0.f;
        } else {
            float Ei = P[i], invE = 1.f / Ei;
            float s2[8], m2 = -3.0e38f;
#pragma unroll
            for (int u = 0; u < 8; u++) {
                if (32 * u < i) {
                    int j = lane + 32 * u;
                    bool valid = (j < i);
                    float r = fmaxf((Ei - P[j + 1]) * invE, 0.f);
                    float pos = valid ? (float)(i - j) : 0.f;
                    float dist = sqrtf(r * pos);
                    float eff = fmaxf(__expf(-ag * dist), 1e-5f);
                    s2[u] = valid ? sc[j] * eff : -3.0e38f;
                    m2 = fmaxf(m2, s2[u]);
                } else s2[u] = -3.0e38f;
            }
            m2 = warp_max(m2);
            float ls = 0.f, ww[8];
#pragma unroll
            for (int u = 0; u < 8; u++) {
                if (32 * u < i) { ww[u] = __expf(s2[u] - m2); ls += ww[u]; }
                else ww[u] = 0.f;
            }
            float sum2 = warp_sum(ls);
            float f = fminf(sum2, 5.f) / sum2;   // maxout folded in
#pragma unroll
            for (int u = 0; u < 8; u++) p[u] = ww[u] * f;
        }
        float* krow = ksbase + (size_t)i * 4096;
#pragma unroll
        for (int u = 0; u < 8; u++) krow[lane + 32 * u] = p[u];
        float acc[16];
#pragma unroll
        for (int d = 0; d < 16; d++) acc[d] = 0.f;
#pragma unroll
        for (int u = 0; u < 8; u++) {
            if (32 * u < i) {
                int j = lane + 32 * u;
                float pv = p[u];
#pragma unroll
                for (int c = 0; c < 4; c++) {
                    float4 vv = *(const float4*)&Vs[j * 20 + c * 4];
                    acc[c*4] += pv*vv.x; acc[c*4+1] += pv*vv.y;
                    acc[c*4+2] += pv*vv.z; acc[c*4+3] += pv*vv.w;
                }
            }
        }
        float vr = xreduce16(acc, lane);
        if (!(lane & 1))
            g_AO4[((size_t)((b * 16 + nk) * 256 + i)) * 128 + h * 16 + (lane >> 1)] = vr;
    }
}

extern "C" void kernel_launch(void* const* d_in, const int* in_sizes, int n_in,
                              void* d_out, int out_size) {
    const float* q_emb = (const float*)d_in[0];
    const float* s_emb = (const float*)d_in[1];
    const float* b1_Wq = (const float*)d_in[3];
    const float* b1_bq = (const float*)d_in[4];
    const float* b1_Wv = (const float*)d_in[5];
    const float* b1_bv = (const float*)d_in[6];
    const float* b1_Wo = (const float*)d_in[7];
    const float* b1_bo = (const float*)d_in[8];
    const float* b1_g  = (const float*)d_in[9];
    const float* b1_lng = (const float*)d_in[10];
    const float* b1_lnb = (const float*)d_in[11];
    const float* b4_Wq = (const float*)d_in[12];
    const float* b4_bq = (const float*)d_in[13];
    const float* b4_Wk = (const float*)d_in[14];
    const float* b4_bk = (const float*)d_in[15];
    const float* b4_Wv = (const float*)d_in[16];
    const float* b4_bv = (const float*)d_in[17];
    const float* b4_Wo = (const float*)d_in[18];
    const float* b4_bo = (const float*)d_in[19];
    const float* b4_g  = (const float*)d_in[20];
    const float* b4_lng = (const float*)d_in[21];
    const float* b4_lnb = (const float*)d_in[22];
    const float* know  = (const float*)d_in[23];
    float* z  = (float*)d_out;
    float* qs = z + 2097152;
    float* ks = z + 4194304;

    cudaFuncSetAttribute(attn1_kernel, cudaFuncAttributeMaxDynamicSharedMemorySize, 49152);

    // 1. P1q, P1v, K4t projections (192 blocks)
    k3gemm<<<dim3(64, 1, 3), 256>>>(q_emb, s_emb, b1_Wq, b1_bq,
                                    b1_Wv, b1_bv, b4_Wk, b4_bk);
    // 2. block1 attention -> qs + AO1
    attn1_kernel<<<256, 256, 49152>>>(b1_g, qs);
    // 3. O1 GEMM + res + LN -> p(smem) -> V GEMM -> V4bh (64 blocks)
    fused_pv<<<64, 256>>>(b1_Wo, b1_bo, q_emb, b1_lng, b1_lnb, b4_Wv, b4_bv);
    // 4. block4 attention (inline Q4) -> ks + AO4
    attn4_kernel<<<512, 256>>>(b4_g, ks, know, b4_Wq, b4_bq);
    // 5. O4 GEMM + residual(know) + LN -> z (scattered)
    gemm_lnz<<<256, 256>>>(b4_Wo, b4_bo, know, b4_lng, b4_lnb, z);
}

// round 12
// speedup vs baseline: 1.3763x; 1.0748x over previous
#include <cuda_runtime.h>

#define FULLMASK 0xffffffffu

__device__ __forceinline__ float warp_sum(float v) {
#pragma unroll
    for (int o = 16; o; o >>= 1) v += __shfl_xor_sync(FULLMASK, v, o);
    return v;
}
__device__ __forceinline__ float warp_max(float v) {
#pragma unroll
    for (int o = 16; o; o >>= 1) v = fmaxf(v, __shfl_xor_sync(FULLMASK, v, o));
    return v;
}

// ---- packed f32x2 helpers (Blackwell FFMA2) ----
__device__ __forceinline__ unsigned long long pack2(float x) {
    unsigned long long r; unsigned int u = __float_as_uint(x);
    asm("mov.b64 %0, {%1, %1};" : "=l"(r) : "r"(u));
    return r;
}
__device__ __forceinline__ void fma2(unsigned long long& acc, unsigned long long v,
                                     unsigned long long p) {
    asm("fma.rn.f32x2 %0, %1, %2, %0;" : "+l"(acc) : "l"(v), "l"(p));
}
__device__ __forceinline__ float2 unpack2(unsigned long long v) {
    unsigned int lo, hi;
    asm("mov.b64 {%0, %1}, %2;" : "=r"(lo), "=r"(hi) : "l"(v));
    return make_float2(__uint_as_float(lo), __uint_as_float(hi));
}

// Transpose-reduce: acc[16] per lane -> full 32-lane sum of element (lane>>1)&15
// on every lane; even lanes are canonical writers. 16 shuffles.
__device__ __forceinline__ float xreduce16(const float acc[16], int lane) {
    float b8[8];
#pragma unroll
    for (int i = 0; i < 8; i++) {
        float send = (lane & 16) ? acc[i] : acc[i + 8];
        float recv = __shfl_xor_sync(FULLMASK, send, 16);
        b8[i] = ((lane & 16) ? acc[i + 8] : acc[i]) + recv;
    }
    float b4[4];
#pragma unroll
    for (int i = 0; i < 4; i++) {
        float send = (lane & 8) ? b8[i] : b8[i + 4];
        float recv = __shfl_xor_sync(FULLMASK, send, 8);
        b4[i] = ((lane & 8) ? b8[i + 4] : b8[i]) + recv;
    }
    float b2[2];
#pragma unroll
    for (int i = 0; i < 2; i++) {
        float send = (lane & 4) ? b4[i] : b4[i + 2];
        float recv = __shfl_xor_sync(FULLMASK, send, 4);
        b2[i] = ((lane & 4) ? b4[i + 2] : b4[i]) + recv;
    }
    float send = (lane & 2) ? b2[0] : b2[1];
    float recv = __shfl_xor_sync(FULLMASK, send, 2);
    float v = ((lane & 2) ? b2[1] : b2[0]) + recv;
    v += __shfl_xor_sync(FULLMASK, v, 1);
    return v;
}

// Packed GEMV step: acc2[8] += Vs[j*20 .. +16) * p  (16 dims as 8 f32x2)
__device__ __forceinline__ void gemv_step(unsigned long long acc2[8],
                                          const float* Vs, int j, float pv) {
    unsigned long long pp = pack2(pv);
    const ulonglong2* vp = (const ulonglong2*)&Vs[j * 20];
    ulonglong2 v0 = vp[0], v1 = vp[1], v2 = vp[2], v3 = vp[3];
    fma2(acc2[0], v0.x, pp); fma2(acc2[1], v0.y, pp);
    fma2(acc2[2], v1.x, pp); fma2(acc2[3], v1.y, pp);
    fma2(acc2[4], v2.x, pp); fma2(acc2[5], v2.y, pp);
    fma2(acc2[6], v3.x, pp); fma2(acc2[7], v3.y, pp);
}

// ---------------- static scratch ----------------
__device__ __align__(16) float g_P1q[1024 * 128];
__device__ __align__(16) float g_P1v[1024 * 128];
__device__ __align__(16) float g_AO1[1024 * 128];
__device__ __align__(16) float g_K4t[1024 * 128];   // (B,H,DK,S)
__device__ __align__(16) float g_V4bh[1024 * 128];  // (B,H,S,DK)
__device__ __align__(16) float g_AO4[16384 * 128];

// ========== 16-row GEMM core ==========
__device__ __forceinline__ void gcore16(const float* __restrict__ A,
                                        const float* __restrict__ W,
                                        int row0, float acc[2][4],
                                        float* As /*32*17*/, float* Ws /*32*128*/) {
    const int t = threadIdx.x;
    const int rg = t >> 5, cg = t & 31;
    const int lr = t >> 4, lk2 = (t & 15) * 2;
    const int wc = t & 127, kh = (t >> 7) * 16;
#pragma unroll
    for (int r = 0; r < 2; r++) { acc[r][0] = acc[r][1] = acc[r][2] = acc[r][3] = 0.f; }
    for (int kb = 0; kb < 128; kb += 32) {
        float2 a = *(const float2*)&A[(size_t)(row0 + lr) * 128 + kb + lk2];
        As[lk2 * 17 + lr] = a.x;
        As[(lk2 + 1) * 17 + lr] = a.y;
#pragma unroll
        for (int q = 0; q < 4; q++) {
            float4 wv = *(const float4*)&W[(size_t)wc * 128 + kb + kh + q * 4];
            Ws[(kh + q * 4 + 0) * 128 + wc] = wv.x;
            Ws[(kh + q * 4 + 1) * 128 + wc] = wv.y;
            Ws[(kh + q * 4 + 2) * 128 + wc] = wv.z;
            Ws[(kh + q * 4 + 3) * 128 + wc] = wv.w;
        }
        __syncthreads();
#pragma unroll
        for (int k = 0; k < 32; k++) {
            float4 wv = *(const float4*)&Ws[k * 128 + cg * 4];
#pragma unroll
            for (int r = 0; r < 2; r++) {
                float a2 = As[k * 17 + rg * 2 + r];
                acc[r][0] += a2 * wv.x; acc[r][1] += a2 * wv.y;
                acc[r][2] += a2 * wv.z; acc[r][3] += a2 * wv.w;
            }
        }
        __syncthreads();
    }
}

// ---- launch 1: three independent projections. z=0: P1q, z=1: P1v, z=2: K4t
__global__ __launch_bounds__(256) void k3gemm(
    const float* __restrict__ q_emb, const float* __restrict__ s_emb,
    const float* __restrict__ Wq1, const float* __restrict__ bq1,
    const float* __restrict__ Wv1, const float* __restrict__ bv1,
    const float* __restrict__ Wk4, const float* __restrict__ bk4) {
    __shared__ float As[32 * 17];
    __shared__ __align__(16) float Ws[32 * 128];
    const int z = blockIdx.z, row0 = blockIdx.x * 16;
    const int t = threadIdx.x, rg = t >> 5, cg = t & 31;
    const float *A, *W, *Bv;
    if (z == 0)      { A = q_emb; W = Wq1; Bv = bq1; }
    else if (z == 1) { A = s_emb; W = Wv1; Bv = bv1; }
    else             { A = q_emb; W = Wk4; Bv = bk4; }
    float acc[2][4];
    gcore16(A, W, row0, acc, As, Ws);
    float4 bv = *(const float4*)&Bv[cg * 4];
#pragma unroll
    for (int r = 0; r < 2; r++) {
        int row = row0 + rg * 2 + r;
        float v[4] = {acc[r][0] + bv.x, acc[r][1] + bv.y,
                      acc[r][2] + bv.z, acc[r][3] + bv.w};
        if (z == 0) {
            *(float4*)&g_P1q[(size_t)row * 128 + cg * 4] = make_float4(v[0], v[1], v[2], v[3]);
        } else if (z == 1) {
            *(float4*)&g_P1v[(size_t)row * 128 + cg * 4] = make_float4(v[0], v[1], v[2], v[3]);
        } else {
            int b = row >> 8, j = row & 255;
#pragma unroll
            for (int i = 0; i < 4; i++) {
                int c = cg * 4 + i, h = c >> 4, dk = c & 15;
                g_K4t[((size_t)((b * 8 + h) * 16 + dk)) * 256 + j] = v[i];
            }
        }
    }
}

// ---- launch 3: O1 GEMM + residual + LN -> p (smem) -> V GEMM -> V4bh
__global__ __launch_bounds__(256) void fused_pv(
    const float* __restrict__ Wo1, const float* __restrict__ bo1,
    const float* __restrict__ q_emb,
    const float* __restrict__ lng, const float* __restrict__ lnb,
    const float* __restrict__ Wv4, const float* __restrict__ bv4) {
    __shared__ float As[32 * 17];
    __shared__ __align__(16) float Ws[32 * 128];
    __shared__ __align__(16) float Ps[16 * 128];
    const int t = threadIdx.x, rg = t >> 5, cg = t & 31;
    const int row0 = blockIdx.x * 16;
    float acc[2][4];
    gcore16(g_AO1, Wo1, row0, acc, As, Ws);
    {
        float4 bv = *(const float4*)&bo1[cg * 4];
        float4 gv = *(const float4*)&lng[cg * 4];
        float4 bb = *(const float4*)&lnb[cg * 4];
#pragma unroll
        for (int r = 0; r < 2; r++) {
            int row = row0 + rg * 2 + r;
            float4 xv = *(const float4*)&q_emb[(size_t)row * 128 + cg * 4];
            float v0 = acc[r][0] + bv.x + xv.x, v1 = acc[r][1] + bv.y + xv.y;
            float v2 = acc[r][2] + bv.z + xv.z, v3 = acc[r][3] + bv.w + xv.w;
            float s1 = warp_sum(v0 + v1 + v2 + v3);
            float s2 = warp_sum(v0 * v0 + v1 * v1 + v2 * v2 + v3 * v3);
            float mean = s1 * (1.f / 128.f);
            float var = s2 * (1.f / 128.f) - mean * mean;
            float rstd = rsqrtf(var + 1e-5f);
            *(float4*)&Ps[(rg * 2 + r) * 128 + cg * 4] =
                make_float4((v0 - mean) * rstd * gv.x + bb.x, (v1 - mean) * rstd * gv.y + bb.y,
                            (v2 - mean) * rstd * gv.z + bb.z, (v3 - mean) * rstd * gv.w + bb.w);
        }
    }
    __syncthreads();
    const int wc = t & 127, kh = (t >> 7) * 16;
    float vac[2][4];
#pragma unroll
    for (int r = 0; r < 2; r++) { vac[r][0] = vac[r][1] = vac[r][2] = vac[r][3] = 0.f; }
    for (int kb = 0; kb < 128; kb += 32) {
#pragma unroll
        for (int q = 0; q < 4; q++) {
            float4 wv = *(const float4*)&Wv4[(size_t)wc * 128 + kb + kh + q * 4];
            Ws[(kh + q * 4 + 0) * 128 + wc] = wv.x;
            Ws[(kh + q * 4 + 1) * 128 + wc] = wv.y;
            Ws[(kh + q * 4 + 2) * 128 + wc] = wv.z;
            Ws[(kh + q * 4 + 3) * 128 + wc] = wv.w;
        }
        __syncthreads();
#pragma unroll
        for (int k = 0; k < 32; k++) {
            float4 wv = *(const float4*)&Ws[k * 128 + cg * 4];
#pragma unroll
            for (int r = 0; r < 2; r++) {
                float a2 = Ps[(rg * 2 + r) * 128 + kb + k];
                vac[r][0] += a2 * wv.x; vac[r][1] += a2 * wv.y;
                vac[r][2] += a2 * wv.z; vac[r][3] += a2 * wv.w;
            }
        }
        __syncthreads();
    }
    float4 bv = *(const float4*)&bv4[cg * 4];
#pragma unroll
    for (int r = 0; r < 2; r++) {
        int row = row0 + rg * 2 + r;
        int b = row >> 8, j = row & 255;
        float v[4] = {vac[r][0] + bv.x, vac[r][1] + bv.y,
                      vac[r][2] + bv.z, vac[r][3] + bv.w};
#pragma unroll
        for (int i = 0; i < 4; i++) {
            int c = cg * 4 + i, h = c >> 4, dk = c & 15;
            g_V4bh[((size_t)((b * 8 + h) * 256 + j)) * 16 + dk] = v[i];
        }
    }
}

// ========== 64-row GEMM core (for the big O4 GEMM) ==========
__device__ __forceinline__ void gcore64(const float* __restrict__ A,
                                        const float* __restrict__ W,
                                        int row0, float acc[8][4],
                                        float* As, float* Ws) {
    const int t = threadIdx.x;
    const int rg = t >> 5, cg = t & 31;
    const int lr = t >> 2, lk = (t & 3) * 8;
    const int wc = t & 127, kh = (t >> 7) * 16;
#pragma unroll
    for (int r = 0; r < 8; r++) { acc[r][0] = acc[r][1] = acc[r][2] = acc[r][3] = 0.f; }
    for (int kb = 0; kb < 128; kb += 32) {
        float4 a0 = *(const float4*)&A[(size_t)(row0 + lr) * 128 + kb + lk];
        float4 a1 = *(const float4*)&A[(size_t)(row0 + lr) * 128 + kb + lk + 4];
        As[(lk + 0) * 65 + lr] = a0.x; As[(lk + 1) * 65 + lr] = a0.y;
        As[(lk + 2) * 65 + lr] = a0.z; As[(lk + 3) * 65 + lr] = a0.w;
        As[(lk + 4) * 65 + lr] = a1.x; As[(lk + 5) * 65 + lr] = a1.y;
        As[(lk + 6) * 65 + lr] = a1.z; As[(lk + 7) * 65 + lr] = a1.w;
#pragma unroll
        for (int q = 0; q < 4; q++) {
            float4 wv = *(const float4*)&W[(size_t)wc * 128 + kb + kh + q * 4];
            Ws[(kh + q * 4 + 0) * 128 + wc] = wv.x;
            Ws[(kh + q * 4 + 1) * 128 + wc] = wv.y;
            Ws[(kh + q * 4 + 2) * 128 + wc] = wv.z;
            Ws[(kh + q * 4 + 3) * 128 + wc] = wv.w;
        }
        __syncthreads();
#pragma unroll
        for (int k = 0; k < 32; k++) {
            float4 wv = *(const float4*)&Ws[k * 128 + cg * 4];
#pragma unroll
            for (int r = 0; r < 8; r++) {
                float a = As[k * 65 + rg * 8 + r];
                acc[r][0] += a * wv.x; acc[r][1] += a * wv.y;
                acc[r][2] += a * wv.z; acc[r][3] += a * wv.w;
            }
        }
        __syncthreads();
    }
}

// ---- launch 5: O4 GEMM + residual(know[nk]) + LN -> z (scattered)
__global__ __launch_bounds__(256) void gemm_lnz(
    const float* __restrict__ W, const float* __restrict__ Bv,
    const float* __restrict__ know,
    const float* __restrict__ lng, const float* __restrict__ lnb,
    float* __restrict__ z) {
    __shared__ float As[32 * 65];
    __shared__ __align__(16) float Ws[32 * 128];
    const int t = threadIdx.x, rg = t >> 5, cg = t & 31;
    const int row0 = blockIdx.x * 64;
    float acc[8][4];
    gcore64(g_AO4, W, row0, acc, As, Ws);
    float4 bv = *(const float4*)&Bv[cg * 4];
    float4 gv = *(const float4*)&lng[cg * 4];
    float4 bb = *(const float4*)&lnb[cg * 4];
#pragma unroll
    for (int r = 0; r < 8; r++) {
        int row = row0 + rg * 8 + r;          // (b*16+nk)*256 + si
        int b = row >> 12, nk = (row >> 8) & 15, si = row & 255;
        float4 xv = *(const float4*)&know[(size_t)nk * 128 + cg * 4];
        float v0 = acc[r][0] + bv.x + xv.x, v1 = acc[r][1] + bv.y + xv.y;
        float v2 = acc[r][2] + bv.z + xv.z, v3 = acc[r][3] + bv.w + xv.w;
        float s1 = warp_sum(v0 + v1 + v2 + v3);
        float s2 = warp_sum(v0 * v0 + v1 * v1 + v2 * v2 + v3 * v3);
        float mean = s1 * (1.f / 128.f);
        float var = s2 * (1.f / 128.f) - mean * mean;
        float rstd = rsqrtf(var + 1e-5f);
        *(float4*)&z[((size_t)(b * 256 + si) * 2048) + nk * 128 + cg * 4] =
            make_float4((v0 - mean) * rstd * gv.x + bb.x, (v1 - mean) * rstd * gv.y + bb.y,
                        (v2 - mean) * rstd * gv.z + bb.z, (v3 - mean) * rstd * gv.w + bb.w);
    }
}

// ---- block1 attention. grid 512 = B*H*16 bands of 16 rows.
__global__ __launch_bounds__(256) void attn1_kernel(
    const float* __restrict__ gamma, float* __restrict__ qscore) {
    extern __shared__ __align__(16) float dyn[];
    float* Ks = dyn;                 // 256*20
    float* Vs = dyn + 5120;          // 256*20
    float* rowbuf = dyn + 10240;     // 8*256
    const int bx = blockIdx.x;
    const int band = bx & 15, h = (bx >> 4) & 7, b = bx >> 7;
    const int t = threadIdx.x, lane = t & 31, w = t >> 5;
    const int umax = band >> 1;      // j<=i possible only for u <= umax
    {
        const float* ksrc = g_P1q + ((size_t)(b * 256 + t)) * 128 + h * 16;
        const float* vsrc = g_P1v + ((size_t)(b * 256 + t)) * 128 + h * 16;
#pragma unroll
        for (int c = 0; c < 4; c++) {
            *(float4*)&Ks[t * 20 + c * 4] = *(const float4*)&ksrc[c * 4];
            *(float4*)&Vs[t * 20 + c * 4] = *(const float4*)&vsrc[c * 4];
        }
    }
    __syncthreads();
    const float ag = fabsf(gamma[h]);
    float* myrow = rowbuf + w * 256;
    for (int it = 0; it < 2; it++) {
        const int i = band * 16 + it * 8 + w;
        float q[16];
#pragma unroll
        for (int c = 0; c < 4; c++) {
            float4 qv = *(const float4*)&Ks[i * 20 + c * 4];
            q[c * 4] = qv.x; q[c * 4 + 1] = qv.y; q[c * 4 + 2] = qv.z; q[c * 4 + 3] = qv.w;
        }
        float sc[8], m1 = -3.0e38f;
#pragma unroll
        for (int u = 0; u < 8; u++) {
            if (u <= umax) {
                int j = lane + 32 * u;
                float s = 0.f;
#pragma unroll
                for (int c = 0; c < 4; c++) {
                    float4 kv = *(const float4*)&Ks[j * 20 + c * 4];
                    s += q[c*4]*kv.x + q[c*4+1]*kv.y + q[c*4+2]*kv.z + q[c*4+3]*kv.w;
                }
                sc[u] = s * 0.25f;
                if (j <= i) m1 = fmaxf(m1, sc[u]);
            }
        }
        m1 = warp_max(m1);
        float lsum = 0.f;
#pragma unroll
        for (int u = 0; u < 8; u++) {
            if (u <= umax) {
                int j = lane + 32 * u;
                lsum += (j <= i) ? __expf(sc[u] - m1) : 0.f;
                myrow[j] = sc[u];
            }
        }
        float inv1 = __fdividef(1.f, warp_sum(lsum));
        __syncwarp();
        // blocked phase: lane owns j in [8*lane, 8*lane+8)
        float scb[8], eb[8], cpref[8], run = 0.f;
#pragma unroll
        for (int o = 0; o < 8; o++) {
            int j = lane * 8 + o;
            scb[o] = myrow[j];
            eb[o] = (j <= i) ? __expf(scb[o] - m1) : 0.f;
            run += eb[o]; cpref[o] = run;
        }
        float x = run;
#pragma unroll
        for (int d = 1; d < 32; d <<= 1) {
            float n = __shfl_up_sync(FULLMASK, x, d);
            if (lane >= d) x += n;
        }
        float excl = x - run;
        float s2[8], m2 = -3.0e38f;
#pragma unroll
        for (int o = 0; o < 8; o++) {
            int j = lane * 8 + o;
            bool valid = (j <= i);
            float c = (cpref[o] + excl) * inv1;
            float pos = valid ? (float)(i - j) : 0.f;
            float dist = sqrtf(fmaxf(1.f - c, 0.f) * pos);
            float eff = fmaxf(__expf(-ag * dist), 1e-5f);
            s2[o] = valid ? scb[o] * eff : -3.0e38f;
            m2 = fmaxf(m2, s2[o]);
        }
        m2 = warp_max(m2);
        float ww[8], ls = 0.f;
#pragma unroll
        for (int o = 0; o < 8; o++) { ww[o] = __expf(s2[o] - m2); ls += ww[o]; }
        float inv2 = __fdividef(1.f, warp_sum(ls));
        float p[8];
#pragma unroll
        for (int o = 0; o < 8; o++) p[o] = ww[o] * inv2;
        float* qrow = qscore + ((size_t)((b * 8 + h) * 256 + i)) * 256;
        *(float4*)&qrow[lane * 8] = make_float4(p[0], p[1], p[2], p[3]);
        *(float4*)&qrow[lane * 8 + 4] = make_float4(p[4], p[5], p[6], p[7]);
        __syncwarp();
#pragma unroll
        for (int o = 0; o < 8; o++) myrow[lane * 8 + o] = p[o];
        __syncwarp();
        unsigned long long acc2[8];
#pragma unroll
        for (int d = 0; d < 8; d++) acc2[d] = 0ull;
#pragma unroll
        for (int u = 0; u < 8; u++) {
            if (u <= umax) {
                int j = lane + 32 * u;
                gemv_step(acc2, Vs, j, myrow[j]);
            }
        }
        float acc[16];
#pragma unroll
        for (int d = 0; d < 8; d++) {
            float2 f2 = unpack2(acc2[d]);
            acc[d * 2] = f2.x; acc[d * 2 + 1] = f2.y;
        }
        float v = xreduce16(acc, lane);
        if (!(lane & 1))
            g_AO1[((size_t)(b * 256 + i)) * 128 + h * 16 + (lane >> 1)] = v;
        __syncwarp();
    }
}

// ---- block4 attention. Row-invariant scores + prefix trick.
// grid 2048 = B(4)*NK(16)*H(8)*SL(4); warp handles i = sl*8+w+32k, k<8 (balanced).
__global__ __launch_bounds__(256) void attn4_kernel(
    const float* __restrict__ gamma, float* __restrict__ kscore,
    const float* __restrict__ know, const float* __restrict__ Wq,
    const float* __restrict__ bq) {
    __shared__ __align__(16) float Vs[256 * 20];
    __shared__ float sc[256];
    __shared__ float qs[16];
    __shared__ float red[8];
    __shared__ float P[257];
    const int bx = blockIdx.x;
    const int h = bx & 7, nk = (bx >> 3) & 15, b = (bx >> 7) & 3, sl = bx >> 9;
    const int t = threadIdx.x, lane = t & 31, w = t >> 5;
    // inline Q4: warp w computes dk = 2w, 2w+1
#pragma unroll
    for (int s = 0; s < 2; s++) {
        int dk = w * 2 + s;
        const float* wr = Wq + (size_t)(h * 16 + dk) * 128;
        float4 wv = *(const float4*)&wr[lane * 4];
        float4 kn = *(const float4*)&know[(size_t)nk * 128 + lane * 4];
        float part = wv.x * kn.x + wv.y * kn.y + wv.z * kn.z + wv.w * kn.w;
        float tot = warp_sum(part);
        if (lane == 0) qs[dk] = tot + bq[h * 16 + dk];
    }
    __syncthreads();
    {
        const float* kb = g_K4t + ((size_t)((b * 8 + h) * 16)) * 256;
        float s = 0.f;
#pragma unroll
        for (int dk = 0; dk < 16; dk++) s += qs[dk] * kb[dk * 256 + t];
        sc[t] = s * 0.25f;
        const float* vsrc = g_V4bh + ((size_t)((b * 8 + h) * 256 + t)) * 16;
#pragma unroll
        for (int c = 0; c < 4; c++)
            *(float4*)&Vs[t * 20 + c * 4] = *(const float4*)&vsrc[c * 4];
    }
    __syncthreads();
    float myv = sc[t];
    float wm = warp_max(myv);
    if (lane == 0) red[w] = wm;
    __syncthreads();
    float M = red[0];
#pragma unroll
    for (int k = 1; k < 8; k++) M = fmaxf(M, red[k]);
    float e = __expf(myv - M);
    float v = e;
#pragma unroll
    for (int d = 1; d < 32; d <<= 1) {
        float n = __shfl_up_sync(FULLMASK, v, d);
        if (lane >= d) v += n;
    }
    __syncthreads();
    if (lane == 31) red[w] = v;
    __syncthreads();
    float off = 0.f;
    for (int k = 0; k < w; k++) off += red[k];
    P[t + 1] = v + off;
    if (t == 0) P[0] = 0.f;
    __syncthreads();
    const float ag = fabsf(gamma[h]);
    float* ksbase = kscore + ((size_t)(b * 8 + h)) * 1048576 + (size_t)nk * 256;
    const int s8w = sl * 8 + w;
#pragma unroll 1
    for (int k = 0; k < 8; k++) {
        const int i = s8w + 32 * k;
        float p[8];
        if (i == 0) {
#pragma unroll
            for (int u = 0; u < 8; u++) p[u] = 0.f;
        } else {
            float Ei = P[i], invE = __fdividef(1.f, Ei);
            float fpos = (float)(i - lane);
            float s2[8], m2 = -3.0e38f;
#pragma unroll
            for (int u = 0; u < 8; u++) {
                if (32 * u < i) {
                    int j = lane + 32 * u;
                    bool valid = (j < i);
                    float r = fmaxf((Ei - P[j + 1]) * invE, 0.f);
                    float pos = valid ? (fpos - 32.f * u) : 0.f;
                    float dist = sqrtf(r * pos);
                    float eff = fmaxf(__expf(-ag * dist), 1e-5f);
                    s2[u] = valid ? sc[j] * eff : -3.0e38f;
                    m2 = fmaxf(m2, s2[u]);
                } else s2[u] = -3.0e38f;
            }
            m2 = warp_max(m2);
            float ls = 0.f, ww[8];
#pragma unroll
            for (int u = 0; u < 8; u++) {
                if (32 * u < i) { ww[u] = __expf(s2[u] - m2); ls += ww[u]; }
                else ww[u] = 0.f;
            }
            float sum2 = warp_sum(ls);
            float f = __fdividef(fminf(sum2, 5.f), sum2);   // maxout folded in
#pragma unroll
            for (int u = 0; u < 8; u++) p[u] = ww[u] * f;
        }
        float* krow = ksbase + (size_t)i * 4096;
#pragma unroll
        for (int u = 0; u < 8; u++) krow[lane + 32 * u] = p[u];
        unsigned long long acc2[8];
#pragma unroll
        for (int d = 0; d < 8; d++) acc2[d] = 0ull;
#pragma unroll
        for (int u = 0; u < 8; u++) {
            if (32 * u < i) {
                int j = lane + 32 * u;
                gemv_step(acc2, Vs, j, p[u]);
            }
        }
        float acc[16];
#pragma unroll
        for (int d = 0; d < 8; d++) {
            float2 f2 = unpack2(acc2[d]);
            acc[d * 2] = f2.x; acc[d * 2 + 1] = f2.y;
        }
        float vr = xreduce16(acc, lane);
        if (!(lane & 1))
            g_AO4[((size_t)((b * 16 + nk) * 256 + i)) * 128 + h * 16 + (lane >> 1)] = vr;
    }
}

extern "C" void kernel_launch(void* const* d_in, const int* in_sizes, int n_in,
                              void* d_out, int out_size) {
    const float* q_emb = (const float*)d_in[0];
    const float* s_emb = (const float*)d_in[1];
    const float* b1_Wq = (const float*)d_in[3];
    const float* b1_bq = (const float*)d_in[4];
    const float* b1_Wv = (const float*)d_in[5];
    const float* b1_bv = (const float*)d_in[6];
    const float* b1_Wo = (const float*)d_in[7];
    const float* b1_bo = (const float*)d_in[8];
    const float* b1_g  = (const float*)d_in[9];
    const float* b1_lng = (const float*)d_in[10];
    const float* b1_lnb = (const float*)d_in[11];
    const float* b4_Wq = (const float*)d_in[12];
    const float* b4_bq = (const float*)d_in[13];
    const float* b4_Wk = (const float*)d_in[14];
    const float* b4_bk = (const float*)d_in[15];
    const float* b4_Wv = (const float*)d_in[16];
    const float* b4_bv = (const float*)d_in[17];
    const float* b4_Wo = (const float*)d_in[18];
    const float* b4_bo = (const float*)d_in[19];
    const float* b4_g  = (const float*)d_in[20];
    const float* b4_lng = (const float*)d_in[21];
    const float* b4_lnb = (const float*)d_in[22];
    const float* know  = (const float*)d_in[23];
    float* z  = (float*)d_out;
    float* qs = z + 2097152;
    float* ks = z + 4194304;

    cudaFuncSetAttribute(attn1_kernel, cudaFuncAttributeMaxDynamicSharedMemorySize, 49152);

    // 1. P1q, P1v, K4t projections (192 blocks)
    k3gemm<<<dim3(64, 1, 3), 256>>>(q_emb, s_emb, b1_Wq, b1_bq,
                                    b1_Wv, b1_bv, b4_Wk, b4_bk);
    // 2. block1 attention -> qs + AO1 (512 blocks, 16-row bands)
    attn1_kernel<<<512, 256, 49152>>>(b1_g, qs);
    // 3. O1 GEMM + res + LN -> p(smem) -> V GEMM -> V4bh (64 blocks)
    fused_pv<<<64, 256>>>(b1_Wo, b1_bo, q_emb, b1_lng, b1_lnb, b4_Wv, b4_bv);
    // 4. block4 attention (inline Q4, 4-way row split) -> ks + AO4
    attn4_kernel<<<2048, 256>>>(b4_g, ks, know, b4_Wq, b4_bq);
    // 5. O4 GEMM + residual(know) + LN -> z (scattered)
    gemm_lnz<<<256, 256>>>(b4_Wo, b4_bo, know, b4_lng, b4_lnb, z);
}